// round 12
// baseline (speedup 1.0000x reference)
#include <cuda_runtime.h>
#include <cuda_bf16.h>
#include <cstdint>

#define BQ   128
#define TQ   1024
#define HQ   256
#define GQ   1024          // 4H
#define INQ  128
#define MROWS (BQ*TQ)      // 131072

// ---------------- scratch (device globals: no allocation allowed) ----------
__device__ float g_xg[(size_t)MROWS * GQ];           // 512 MB: input-gate preacts
__device__ __nv_bfloat16 g_ahi[(size_t)MROWS * HQ];  // 64 MB: A hi (bf16)
__device__ __nv_bfloat16 g_alo[(size_t)MROWS * HQ];  // 64 MB: A lo (bf16)
__device__ __nv_bfloat16 g_whi[GQ * HQ];             // W hi (bf16)
__device__ __nv_bfloat16 g_wlo[GQ * HQ];             // W lo (bf16)

// h exchange, fragment-major: [buf][b-group]{ hi 8KB | lo 8KB }
// word addr = i*512B + l*16B + w*4B ; word(l,w) = pair (n = (w&1)*8 + (l>>2),
// k = i*16 + (w>>1)*8 + 2*(l&3)) packed {bf16(k), bf16(k+1)}
__device__ __align__(16) char g_htile[2][8][16384];

#define LGRID 128
#define FLAG_STRIDE 32                               // 128B per flag
__device__ unsigned int g_flags[LGRID * FLAG_STRIDE];

extern __shared__ float4 s4[];

// ---------------- init: reset flags + h tile buf0 ----------------------------
__global__ void init_kernel() {
    int i = blockIdx.x * blockDim.x + threadIdx.x;
    int stride = gridDim.x * blockDim.x;
    for (int k = i; k < LGRID * FLAG_STRIDE; k += stride) g_flags[k] = 0u;
    unsigned* p = (unsigned*)&g_htile[0][0][0];
    for (int k = i; k < 8 * 16384 / 4; k += stride) p[k] = 0u;
}

// ---------------- helpers ----------------------------------------------------
__device__ __forceinline__ void mma16816(float* d, const unsigned* a,
                                         unsigned b0, unsigned b1) {
    asm volatile(
        "mma.sync.aligned.m16n8k16.row.col.f32.bf16.bf16.f32 "
        "{%0,%1,%2,%3}, {%4,%5,%6,%7}, {%8,%9}, {%0,%1,%2,%3};\n"
        : "+f"(d[0]), "+f"(d[1]), "+f"(d[2]), "+f"(d[3])
        : "r"(a[0]), "r"(a[1]), "r"(a[2]), "r"(a[3]), "r"(b0), "r"(b1));
}

__device__ __forceinline__ void ldsm4(unsigned* r, unsigned addr) {
    asm volatile(
        "ldmatrix.sync.aligned.m8n8.x4.shared.b16 {%0,%1,%2,%3}, [%4];\n"
        : "=r"(r[0]), "=r"(r[1]), "=r"(r[2]), "=r"(r[3]) : "r"(addr));
}

// bf16 element (row, k) inside rows x 64k tile: 128B rows, 16B chunks xor row&7
__device__ __forceinline__ unsigned sw_off(int row, int k) {
    return (unsigned)(row * 128 + ((((k >> 3) ^ row) & 7) << 4) + ((k & 7) << 1));
}

__device__ __forceinline__ unsigned pk2(float a, float b) {
    __nv_bfloat162 t(__float2bfloat16_rn(a), __float2bfloat16_rn(b));
    return *(unsigned*)&t;
}

__device__ __forceinline__ void stsv2(unsigned addr, unsigned a, unsigned b) {
    asm volatile("st.shared.v2.b32 [%0], {%1,%2};\n" :: "r"(addr), "r"(a), "r"(b));
}

__device__ __forceinline__ void cpasync16(unsigned dst, const void* src) {
    asm volatile("cp.async.cg.shared.global [%0], [%1], 16;\n" :: "r"(dst), "l"(src));
}

__device__ __forceinline__ float sigf(float x)   { return 1.f / (1.f + __expf(-x)); }
__device__ __forceinline__ float tanhf_(float x) { return 2.f / (1.f + __expf(-2.f * x)) - 1.f; }

// ---------------- fp32 -> bf16 hi/lo split (memory-bound pass) ---------------
__global__ void cvt_split(const float4* __restrict__ src,
                          uint2* __restrict__ hi, uint2* __restrict__ lo, int n4) {
    int i = blockIdx.x * blockDim.x + threadIdx.x;
    if (i >= n4) return;
    float4 v = src[i];
    __nv_bfloat16 h0 = __float2bfloat16_rn(v.x), h1 = __float2bfloat16_rn(v.y);
    __nv_bfloat16 h2 = __float2bfloat16_rn(v.z), h3 = __float2bfloat16_rn(v.w);
    float l0 = v.x - __bfloat162float(h0), l1 = v.y - __bfloat162float(h1);
    float l2 = v.z - __bfloat162float(h2), l3 = v.w - __bfloat162float(h3);
    __nv_bfloat162 t0(h0, h1), t1(h2, h3);
    hi[i] = make_uint2(*(unsigned*)&t0, *(unsigned*)&t1);
    lo[i] = make_uint2(pk2(l0, l1), pk2(l2, l3));
}

// ============================================================================
// Double-buffered cp.async bf16 GEMM, CTA tile 128 x 256 (validated R11,
// 388us big GEMM). C = A(MxK)*Bw(NxK)^T + b1 + b2. K-slab 64, 2 smem stages.
// ============================================================================
#define GT 16384
#define STG_B  (6 * GT)
#define GEMM_SMEM (2 * STG_B)

__global__ void __launch_bounds__(256, 1) gemm_pp(
    const __nv_bfloat16* __restrict__ Ahi, const __nv_bfloat16* __restrict__ Alo,
    const __nv_bfloat16* __restrict__ Bhi, const __nv_bfloat16* __restrict__ Blo,
    const float* __restrict__ b1, const float* __restrict__ b2,
    float* __restrict__ C, int M, int N, int K)
{
    unsigned sbase = (unsigned)__cvta_generic_to_shared((char*)s4);

    const int tid  = threadIdx.x;
    const int lane = tid & 31;
    const int warp = tid >> 5;
    const int wm   = warp & 3;
    const int wn   = warp >> 2;
    const int m0   = blockIdx.y << 7;
    const int n0   = blockIdx.x << 8;
    const int nsub = (N - n0 >= 256) ? 2 : 1;

    const int lrow = tid >> 1;
    const int lc0  = (tid & 1) * 4;

    const __nv_bfloat16* pAh = Ahi + (size_t)(m0 + lrow) * K;
    const __nv_bfloat16* pAl = Alo + (size_t)(m0 + lrow) * K;
    const __nv_bfloat16* pBh = Bhi + (size_t)(n0 + lrow) * K;
    const __nv_bfloat16* pBl = Blo + (size_t)(n0 + lrow) * K;

    float acc[2][16][4];
#pragma unroll
    for (int mt = 0; mt < 2; ++mt)
#pragma unroll
        for (int nt = 0; nt < 16; ++nt)
#pragma unroll
            for (int e = 0; e < 4; ++e) acc[mt][nt][e] = 0.f;

    const int nslab = K >> 6;

    auto issue = [&](int stage, int k0) {
        unsigned sb = sbase + stage * STG_B;
#pragma unroll
        for (int c = 0; c < 4; ++c) {
            int ko = (lc0 + c) << 3;
            unsigned d = sb + sw_off(lrow, ko);
            cpasync16(d,          pAh + k0 + ko);
            cpasync16(d + GT,     pAl + k0 + ko);
            cpasync16(d + 2 * GT, pBh + k0 + ko);
            cpasync16(d + 3 * GT, pBl + k0 + ko);
            if (nsub == 2) {
                cpasync16(d + 4 * GT, pBh + (size_t)128 * K + k0 + ko);
                cpasync16(d + 5 * GT, pBl + (size_t)128 * K + k0 + ko);
            }
        }
        asm volatile("cp.async.commit_group;\n");
    };

    issue(0, 0);

    for (int s = 0; s < nslab; ++s) {
        if (s + 1 < nslab) {
            issue((s + 1) & 1, (s + 1) << 6);
            asm volatile("cp.async.wait_group 1;\n");
        } else {
            asm volatile("cp.async.wait_group 0;\n");
        }
        __syncthreads();

        unsigned sb = sbase + (s & 1) * STG_B;
#pragma unroll
        for (int k16 = 0; k16 < 64; k16 += 16) {
            unsigned ah[2][4], al[2][4];
#pragma unroll
            for (int mt = 0; mt < 2; ++mt) {
                int row = wm * 32 + mt * 16 + (lane & 15);
                int kk  = k16 + ((lane >> 4) << 3);
                unsigned ad = sb + sw_off(row, kk);
                ldsm4(ah[mt], ad);
                ldsm4(al[mt], ad + GT);
            }
#pragma unroll
            for (int sub = 0; sub < 2; ++sub) {
                if (sub >= nsub) break;
                unsigned bbase = sb + (2 + 2 * sub) * GT;
#pragma unroll
                for (int g = 0; g < 4; ++g) {
                    unsigned bh[4], bl[4];
                    int row = wn * 64 + g * 16 + (lane & 15);
                    int kk  = k16 + ((lane >> 4) << 3);
                    unsigned bd = bbase + sw_off(row, kk);
                    ldsm4(bh, bd);
                    ldsm4(bl, bd + GT);
                    int nb = sub * 8 + 2 * g;
#pragma unroll
                    for (int mt = 0; mt < 2; ++mt) {
                        mma16816(acc[mt][nb],     ah[mt], bh[0], bh[2]);
                        mma16816(acc[mt][nb],     ah[mt], bl[0], bl[2]);
                        mma16816(acc[mt][nb],     al[mt], bh[0], bh[2]);
                        mma16816(acc[mt][nb + 1], ah[mt], bh[1], bh[3]);
                        mma16816(acc[mt][nb + 1], ah[mt], bl[1], bl[3]);
                        mma16816(acc[mt][nb + 1], al[mt], bh[1], bh[3]);
                    }
                }
            }
        }
        __syncthreads();
    }

#pragma unroll
    for (int nt = 0; nt < 16; ++nt) {
        int sub = nt >> 3, ntl = nt & 7;
        if (sub >= nsub) break;
        int col = n0 + sub * 128 + wn * 64 + ntl * 8 + ((lane & 3) << 1);
        float bx = 0.f, by = 0.f;
        if (b1) { float2 t = *(const float2*)&b1[col]; bx += t.x; by += t.y; }
        if (b2) { float2 t = *(const float2*)&b2[col]; bx += t.x; by += t.y; }
#pragma unroll
        for (int mt = 0; mt < 2; ++mt) {
            int row = m0 + wm * 32 + mt * 16 + (lane >> 2);
            float2 c0 = make_float2(acc[mt][nt][0] + bx, acc[mt][nt][1] + by);
            float2 c1 = make_float2(acc[mt][nt][2] + bx, acc[mt][nt][3] + by);
            *(float2*)&C[(size_t)row * N + col] = c0;
            *(float2*)&C[(size_t)(row + 8) * N + col] = c1;
        }
    }
}

// ============================================================================
// Recurrent layer: 128 CTAs x 256 threads. CTA: D[64 gates x 16 b], K=256
// split across 2 warp-sets. B consumed fragment-direct from g_htile via
// FULL-prefetch LDG.128 (16 loads back-to-back, MLP=16 — no SMEM staging,
// no cp.async issue cost). h published fragment-major + bf16 hseq deferred.
// ============================================================================
#define MO_AHI 0
#define MO_ALO 32768
#define MO_GB  65536
#define GB_FLOATS 1152
#define LSTM_SMEM_MMA (MO_GB + 2*GB_FLOATS*4 + 64)

__device__ __forceinline__ unsigned aw_off(int row, int k) {
    return (unsigned)((k >> 6) * 8192) + sw_off(row, k & 63);
}

__global__ void __launch_bounds__(256, 1) lstm_mma(
    const float* __restrict__ xg, const float* __restrict__ whh,
    float* __restrict__ outh, float* __restrict__ outc)
{
    char* sm = (char*)s4;
    unsigned sb = (unsigned)__cvta_generic_to_shared(sm);
    float* gb0 = (float*)(sm + MO_GB);
    float* gb1 = gb0 + GB_FLOATS;

    const int tid  = threadIdx.x;
    const int lane = tid & 31;
    const int wid  = tid >> 5;              // 0..7
    const int ws   = wid & 3;               // m-tile set
    const int kh   = wid >> 2;              // K half (0/1)
    const int j0   = (blockIdx.x & 15) * 16;
    const int b0   = (blockIdx.x >> 4) * 16;

    // ---- stage W hi/lo once: 64 rows x 256 k ----
    {
        int row = tid >> 2;                 // 0..63
        int kq  = (tid & 3) * 64;
        int wrow = (row >> 4) * HQ + j0 + (row & 15);
        const float4* wsrc = (const float4*)(whh + (size_t)wrow * HQ + kq);
#pragma unroll
        for (int q = 0; q < 16; ++q) {
            float4 v = wsrc[q];
            __nv_bfloat16 h0 = __float2bfloat16_rn(v.x), h1 = __float2bfloat16_rn(v.y);
            __nv_bfloat16 h2 = __float2bfloat16_rn(v.z), h3 = __float2bfloat16_rn(v.w);
            float l0 = v.x - __bfloat162float(h0), l1 = v.y - __bfloat162float(h1);
            float l2 = v.z - __bfloat162float(h2), l3 = v.w - __bfloat162float(h3);
            __nv_bfloat162 t0(h0, h1), t1(h2, h3);
            int k = kq + q * 4;
            unsigned oa = sb + MO_AHI + aw_off(row, k);
            stsv2(oa, *(unsigned*)&t0, *(unsigned*)&t1);
            stsv2(oa + (MO_ALO - MO_AHI), pk2(l0, l1), pk2(l2, l3));
        }
    }
    __syncthreads();

    // activation: 1 item/thread: jl = tid&15, b = tid>>4
    const int jl = tid & 15;
    const int bA = tid >> 4;
    float cst = 0.f;

    // ldsm addressing (per warp)
    const int arow = ws * 16 + (lane & 15);
    const int ksub = (lane >> 4) << 3;

    // fragment publish coords (jl even): k16 block = this CTA's j-chunk
    const int pub = ((jl & 1) == 0);
    const int fi  = blockIdx.x & 15;
    const int fw  = ((jl >= 8) ? 2 : 0) | ((bA >= 8) ? 1 : 0);
    const int fl  = ((bA & 7) << 2) | ((jl & 7) >> 1);
    const unsigned foff = (unsigned)(fi * 512 + fl * 16 + fw * 4);

    // per-b-group barrier flags
    const int bg = blockIdx.x >> 4;         // 0..7
    const int cg = blockIdx.x & 15;         // 0..15
    unsigned* myflag = &g_flags[(bg * 16 + cg) * FLAG_STRIDE];
    const unsigned* pollp = &g_flags[(bg * 16 + (lane & 15)) * FLAG_STRIDE];

    for (int t = 0; t < TQ; ++t) {
        const int rbuf = t & 1, wbuf = rbuf ^ 1;

        // ---- FULL B prefetch: 16 LDG.128 back-to-back (this warp's K-half) ----
        uint4 bhv[8], blv[8];
        {
            const uint4* fhb = (const uint4*)(&g_htile[rbuf][bg][0]);  // 512 uint4 hi
            const uint4* flb = fhb + 512;                               // lo
            const int fbase = kh * 8 * 32 + lane;
#pragma unroll
            for (int ii = 0; ii < 8; ++ii) bhv[ii] = __ldcg(fhb + fbase + ii * 32);
#pragma unroll
            for (int ii = 0; ii < 8; ++ii) blv[ii] = __ldcg(flb + fbase + ii * 32);
        }

        // prefetch xg_t (4 gates for our item)
        float xv[4];
        {
            const float* p = xg + (((size_t)(b0 + bA) * TQ + t) * GQ) + j0 + jl;
#pragma unroll
            for (int g = 0; g < 4; ++g) xv[g] = __ldcg(p + (g << 8));
        }

        // D[64 x 16] partial (this warp-set's K half = 128), B from regs
        float acc[2][4];
#pragma unroll
        for (int nt = 0; nt < 2; ++nt)
#pragma unroll
            for (int e = 0; e < 4; ++e) acc[nt][e] = 0.f;

#pragma unroll
        for (int ii = 0; ii < 8; ++ii) {
            int kk = (kh * 8 + ii) * 16 + ksub;
            unsigned ka = sb + MO_AHI + aw_off(arow, kk);
            unsigned ah[4], al[4];
            ldsm4(ah, ka);
            ldsm4(al, ka + (MO_ALO - MO_AHI));
            mma16816(acc[0], ah, bhv[ii].x, bhv[ii].z);
            mma16816(acc[0], ah, blv[ii].x, blv[ii].z);
            mma16816(acc[0], al, bhv[ii].x, bhv[ii].z);
            mma16816(acc[1], ah, bhv[ii].y, bhv[ii].w);
            mma16816(acc[1], ah, blv[ii].y, blv[ii].w);
            mma16816(acc[1], al, bhv[ii].y, bhv[ii].w);
        }

        // scatter partials to this K-half's gate buffer
        {
            float* gbk = kh ? gb1 : gb0;
            int rowA = ws * 16 + (lane >> 2);
            int c0   = 2 * (lane & 3);
#pragma unroll
            for (int nt = 0; nt < 2; ++nt) {
                *(float2*)&gbk[rowA * 18 + nt * 8 + c0]       = make_float2(acc[nt][0], acc[nt][1]);
                *(float2*)&gbk[(rowA + 8) * 18 + nt * 8 + c0] = make_float2(acc[nt][2], acc[nt][3]);
            }
        }
        __syncthreads();

        // activation + state update + publish exchange fragment
        float cn, hn;
        unsigned hiw = 0, low = 0;
        {
            int b = bA;
            float pi = gb0[(jl     ) * 18 + b] + gb1[(jl     ) * 18 + b] + xv[0];
            float pf = gb0[(16 + jl) * 18 + b] + gb1[(16 + jl) * 18 + b] + xv[1];
            float pg = gb0[(32 + jl) * 18 + b] + gb1[(32 + jl) * 18 + b] + xv[2];
            float po = gb0[(48 + jl) * 18 + b] + gb1[(48 + jl) * 18 + b] + xv[3];
            float gi = sigf(pi), gf = sigf(pf), gg = tanhf_(pg), go = sigf(po);
            cn = gf * cst + gi * gg;
            cst = cn;
            hn = go * tanhf_(cn);

            // bf16 hi/lo split of hn, packed (hi | lo<<16)
            __nv_bfloat16 hhi = __float2bfloat16_rn(hn);
            float lof = hn - __bfloat162float(hhi);
            __nv_bfloat16 hlo = __float2bfloat16_rn(lof);
            unsigned pck = ((unsigned)*(unsigned short*)&hhi)
                         | (((unsigned)*(unsigned short*)&hlo) << 16);
            unsigned pn  = __shfl_down_sync(0xFFFFFFFFu, pck, 1);

            if (pub) {
                hiw = (pck & 0xFFFFu) | ((pn & 0xFFFFu) << 16);
                low = (pck >> 16)     | (pn & 0xFFFF0000u);
                char* baseh = &g_htile[wbuf][bg][0];
                *(unsigned*)(baseh + foff)        = hiw;
                *(unsigned*)(baseh + 8192 + foff) = low;
            }
        }

        // ---- per-b-group barrier release (exchange fragment visible first) ----
        __syncthreads();
        if (tid == 0)
            asm volatile("st.release.gpu.global.u32 [%0], %1;"
                         :: "l"(myflag), "r"((unsigned)(t + 1)) : "memory");

        // deferred bookkeeping: overlaps peers' polling
        if (pub) {
            size_t hoff = ((size_t)(b0 + bA) * TQ + t) * HQ + j0 + jl;
            *(unsigned*)&g_ahi[hoff] = hiw;
            *(unsigned*)&g_alo[hoff] = low;
        }
        if (t == TQ - 1) {
            int bgl = b0 + bA, jg = j0 + jl;
            outh[bgl * HQ + jg] = hn;
            outc[bgl * HQ + jg] = cn;
        }

        if (wid == 0 && lane < 16) {
            unsigned v;
            do {
                asm volatile("ld.acquire.gpu.global.u32 %0, [%1];"
                             : "=r"(v) : "l"(pollp) : "memory");
            } while (v < (unsigned)(t + 1));
        }
        __syncthreads();
    }
}

// ---------------- launch -----------------------------------------------------
extern "C" void kernel_launch(void* const* d_in, const int* in_sizes, int n_in,
                              void* d_out, int out_size)
{
    const float* x    = (const float*)d_in[0];
    const float* wih0 = (const float*)d_in[1];
    const float* whh0 = (const float*)d_in[2];
    const float* bih0 = (const float*)d_in[3];
    const float* bhh0 = (const float*)d_in[4];
    const float* wih1 = (const float*)d_in[5];
    const float* whh1 = (const float*)d_in[6];
    const float* bih1 = (const float*)d_in[7];
    const float* bhh1 = (const float*)d_in[8];
    const float* wlin = (const float*)d_in[9];
    const float* blin = (const float*)d_in[10];

    float* out  = (float*)d_out;                    // [B,T,In]
    float* outh = out + (size_t)BQ * TQ * INQ;      // [2,B,H]
    float* outc = outh + 2 * BQ * HQ;               // [2,B,H]

    float* p_xg;
    __nv_bfloat16 *p_ahi, *p_alo, *p_whi, *p_wlo;
    cudaGetSymbolAddress((void**)&p_xg,  g_xg);
    cudaGetSymbolAddress((void**)&p_ahi, g_ahi);
    cudaGetSymbolAddress((void**)&p_alo, g_alo);
    cudaGetSymbolAddress((void**)&p_whi, g_whi);
    cudaGetSymbolAddress((void**)&p_wlo, g_wlo);
    cudaFuncSetAttribute(gemm_pp,  cudaFuncAttributeMaxDynamicSharedMemorySize, GEMM_SMEM);
    cudaFuncSetAttribute(lstm_mma, cudaFuncAttributeMaxDynamicSharedMemorySize, LSTM_SMEM_MMA);

    dim3 gg(GQ / 256, MROWS / 128);    // (4, 1024)
    dim3 gf(1, MROWS / 128);           // N=128 -> nsub=1

    const int CB = 256;
    int n4x = MROWS * INQ / 4;

    // ---- layer 0 ----
    cvt_split<<<(n4x + CB - 1) / CB, CB>>>((const float4*)x, (uint2*)p_ahi, (uint2*)p_alo, n4x);
    cvt_split<<<(GQ * INQ / 4 + CB - 1) / CB, CB>>>((const float4*)wih0, (uint2*)p_whi, (uint2*)p_wlo, GQ * INQ / 4);
    init_kernel<<<64, 256>>>();
    gemm_pp<<<gg, 256, GEMM_SMEM>>>(p_ahi, p_alo, p_whi, p_wlo, bih0, bhh0, p_xg, MROWS, GQ, INQ);
    lstm_mma<<<LGRID, 256, LSTM_SMEM_MMA>>>(p_xg, whh0, outh, outc);
    // lstm0 wrote h0seq as bf16 hi/lo into g_ahi/g_alo

    // ---- layer 1 ----
    cvt_split<<<(GQ * HQ / 4 + CB - 1) / CB, CB>>>((const float4*)wih1, (uint2*)p_whi, (uint2*)p_wlo, GQ * HQ / 4);
    init_kernel<<<64, 256>>>();
    gemm_pp<<<gg, 256, GEMM_SMEM>>>(p_ahi, p_alo, p_whi, p_wlo, bih1, bhh1, p_xg, MROWS, GQ, HQ);
    lstm_mma<<<LGRID, 256, LSTM_SMEM_MMA>>>(p_xg, whh1, outh + BQ * HQ, outc + BQ * HQ);
    // lstm1 wrote h1seq as bf16 hi/lo into g_ahi/g_alo

    // ---- final projection ----
    cvt_split<<<(INQ * HQ / 4 + CB - 1) / CB, CB>>>((const float4*)wlin, (uint2*)p_whi, (uint2*)p_wlo, INQ * HQ / 4);
    gemm_pp<<<gf, 256, GEMM_SMEM>>>(p_ahi, p_alo, p_whi, p_wlo, blin, nullptr, out, MROWS, INQ, HQ);
}

// round 14
// speedup vs baseline: 1.3316x; 1.3316x over previous
#include <cuda_runtime.h>
#include <cuda_fp16.h>
#include <cstdint>

#define BQ   128
#define TQ   1024
#define HQ   256
#define GQ   1024          // 4H
#define INQ  128
#define MROWS (BQ*TQ)      // 131072

// ---------------- scratch (device globals: no allocation allowed) ----------
__device__ float g_xg[(size_t)MROWS * GQ];        // 512 MB: input-gate preacts
__device__ __half g_a16[(size_t)MROWS * HQ];      // 64 MB: A operand (fp16)
__device__ __half g_whi[GQ * HQ];                 // W hi (fp16)
__device__ __half g_wlo[GQ * HQ];                 // W lo (fp16)

// h exchange tiles: [buf][b-group]; 8KB used (swizzled fp16 B-tile)
__device__ __align__(16) char g_htile[2][8][16384];

#define LGRID 128
#define FLAG_STRIDE 32                               // 128B per flag
__device__ unsigned int g_flags[LGRID * FLAG_STRIDE];

extern __shared__ float4 s4[];

// ---------------- init: reset flags + h tile buf0 ----------------------------
__global__ void init_kernel() {
    int i = blockIdx.x * blockDim.x + threadIdx.x;
    int stride = gridDim.x * blockDim.x;
    for (int k = i; k < LGRID * FLAG_STRIDE; k += stride) g_flags[k] = 0u;
    unsigned* p = (unsigned*)&g_htile[0][0][0];
    for (int k = i; k < 8 * 16384 / 4; k += stride) p[k] = 0u;
}

// ---------------- helpers ----------------------------------------------------
__device__ __forceinline__ void mma16816h(float* d, const unsigned* a,
                                          unsigned b0, unsigned b1) {
    asm volatile(
        "mma.sync.aligned.m16n8k16.row.col.f32.f16.f16.f32 "
        "{%0,%1,%2,%3}, {%4,%5,%6,%7}, {%8,%9}, {%0,%1,%2,%3};\n"
        : "+f"(d[0]), "+f"(d[1]), "+f"(d[2]), "+f"(d[3])
        : "r"(a[0]), "r"(a[1]), "r"(a[2]), "r"(a[3]), "r"(b0), "r"(b1));
}

__device__ __forceinline__ void ldsm4(unsigned* r, unsigned addr) {
    asm volatile(
        "ldmatrix.sync.aligned.m8n8.x4.shared.b16 {%0,%1,%2,%3}, [%4];\n"
        : "=r"(r[0]), "=r"(r[1]), "=r"(r[2]), "=r"(r[3]) : "r"(addr));
}

// fp16 element (row, k) inside rows x 64k tile: 128B rows, 16B chunks xor row&7
__device__ __forceinline__ unsigned sw_off(int row, int k) {
    return (unsigned)(row * 128 + ((((k >> 3) ^ row) & 7) << 4) + ((k & 7) << 1));
}

__device__ __forceinline__ unsigned pk2h(float a, float b) {
    __half2 t(__float2half_rn(a), __float2half_rn(b));
    return *(unsigned*)&t;
}

__device__ __forceinline__ void stsv2(unsigned addr, unsigned a, unsigned b) {
    asm volatile("st.shared.v2.b32 [%0], {%1,%2};\n" :: "r"(addr), "r"(a), "r"(b));
}

__device__ __forceinline__ void cpasync16(unsigned dst, const void* src) {
    asm volatile("cp.async.cg.shared.global [%0], [%1], 16;\n" :: "r"(dst), "l"(src));
}

__device__ __forceinline__ float sigf(float x)   { return 1.f / (1.f + __expf(-x)); }
__device__ __forceinline__ float tanhf_(float x) { return 2.f / (1.f + __expf(-2.f * x)) - 1.f; }

// ---------------- converts (memory-bound passes) ------------------------------
__global__ void cvt_a(const float4* __restrict__ src, uint2* __restrict__ dst, int n4) {
    int i = blockIdx.x * blockDim.x + threadIdx.x;
    if (i >= n4) return;
    float4 v = src[i];
    dst[i] = make_uint2(pk2h(v.x, v.y), pk2h(v.z, v.w));
}
__global__ void cvt_w(const float4* __restrict__ src,
                      uint2* __restrict__ hi, uint2* __restrict__ lo, int n4) {
    int i = blockIdx.x * blockDim.x + threadIdx.x;
    if (i >= n4) return;
    float4 v = src[i];
    __half h0 = __float2half_rn(v.x), h1 = __float2half_rn(v.y);
    __half h2 = __float2half_rn(v.z), h3 = __float2half_rn(v.w);
    float l0 = v.x - __half2float(h0), l1 = v.y - __half2float(h1);
    float l2 = v.z - __half2float(h2), l3 = v.w - __half2float(h3);
    __half2 t0(h0, h1), t1(h2, h3);
    hi[i] = make_uint2(*(unsigned*)&t0, *(unsigned*)&t1);
    lo[i] = make_uint2(pk2h(l0, l1), pk2h(l2, l3));
}

// ============================================================================
// Double-buffered cp.async fp16 GEMM, CTA tile 128 x 256.
// C = A(MxK)*(Wh+Wl)(NxK)^T + b1 + b2.  A single fp16; W split hi/lo.
// Stage layout: A | B0H | B0L | B1H | B1L (16KB each) = 80KB/stage, 2 stages.
// ============================================================================
#define GT 16384
#define STG_B  (5 * GT)
#define GEMM_SMEM (2 * STG_B)

__global__ void __launch_bounds__(256, 1) gemm_pp(
    const __half* __restrict__ A,
    const __half* __restrict__ Bhi, const __half* __restrict__ Blo,
    const float* __restrict__ b1, const float* __restrict__ b2,
    float* __restrict__ C, int M, int N, int K)
{
    unsigned sbase = (unsigned)__cvta_generic_to_shared((char*)s4);

    const int tid  = threadIdx.x;
    const int lane = tid & 31;
    const int warp = tid >> 5;
    const int wm   = warp & 3;
    const int wn   = warp >> 2;
    const int m0   = blockIdx.y << 7;
    const int n0   = blockIdx.x << 8;
    const int nsub = (N - n0 >= 256) ? 2 : 1;

    const int lrow = tid >> 1;
    const int lc0  = (tid & 1) * 4;

    const __half* pA  = A   + (size_t)(m0 + lrow) * K;
    const __half* pBh = Bhi + (size_t)(n0 + lrow) * K;
    const __half* pBl = Blo + (size_t)(n0 + lrow) * K;

    float acc[2][16][4];
#pragma unroll
    for (int mt = 0; mt < 2; ++mt)
#pragma unroll
        for (int nt = 0; nt < 16; ++nt)
#pragma unroll
            for (int e = 0; e < 4; ++e) acc[mt][nt][e] = 0.f;

    const int nslab = K >> 6;

    auto issue = [&](int stage, int k0) {
        unsigned sb = sbase + stage * STG_B;
#pragma unroll
        for (int c = 0; c < 4; ++c) {
            int ko = (lc0 + c) << 3;
            unsigned d = sb + sw_off(lrow, ko);
            cpasync16(d,          pA  + k0 + ko);
            cpasync16(d + GT,     pBh + k0 + ko);
            cpasync16(d + 2 * GT, pBl + k0 + ko);
            if (nsub == 2) {
                cpasync16(d + 3 * GT, pBh + (size_t)128 * K + k0 + ko);
                cpasync16(d + 4 * GT, pBl + (size_t)128 * K + k0 + ko);
            }
        }
        asm volatile("cp.async.commit_group;\n");
    };

    issue(0, 0);

    for (int s = 0; s < nslab; ++s) {
        if (s + 1 < nslab) {
            issue((s + 1) & 1, (s + 1) << 6);
            asm volatile("cp.async.wait_group 1;\n");
        } else {
            asm volatile("cp.async.wait_group 0;\n");
        }
        __syncthreads();

        unsigned sb = sbase + (s & 1) * STG_B;
#pragma unroll
        for (int k16 = 0; k16 < 64; k16 += 16) {
            unsigned ah[2][4];
#pragma unroll
            for (int mt = 0; mt < 2; ++mt) {
                int row = wm * 32 + mt * 16 + (lane & 15);
                int kk  = k16 + ((lane >> 4) << 3);
                ldsm4(ah[mt], sb + sw_off(row, kk));
            }
#pragma unroll
            for (int sub = 0; sub < 2; ++sub) {
                if (sub >= nsub) break;
                unsigned bbase = sb + (1 + 2 * sub) * GT;
#pragma unroll
                for (int g = 0; g < 4; ++g) {
                    unsigned bh[4], bl[4];
                    int row = wn * 64 + g * 16 + (lane & 15);
                    int kk  = k16 + ((lane >> 4) << 3);
                    unsigned bd = bbase + sw_off(row, kk);
                    ldsm4(bh, bd);
                    ldsm4(bl, bd + GT);
                    int nb = sub * 8 + 2 * g;
#pragma unroll
                    for (int mt = 0; mt < 2; ++mt) {
                        mma16816h(acc[mt][nb],     ah[mt], bh[0], bh[2]);
                        mma16816h(acc[mt][nb],     ah[mt], bl[0], bl[2]);
                        mma16816h(acc[mt][nb + 1], ah[mt], bh[1], bh[3]);
                        mma16816h(acc[mt][nb + 1], ah[mt], bl[1], bl[3]);
                    }
                }
            }
        }
        __syncthreads();
    }

#pragma unroll
    for (int nt = 0; nt < 16; ++nt) {
        int sub = nt >> 3, ntl = nt & 7;
        if (sub >= nsub) break;
        int col = n0 + sub * 128 + wn * 64 + ntl * 8 + ((lane & 3) << 1);
        float bx = 0.f, by = 0.f;
        if (b1) { float2 t = *(const float2*)&b1[col]; bx += t.x; by += t.y; }
        if (b2) { float2 t = *(const float2*)&b2[col]; bx += t.x; by += t.y; }
#pragma unroll
        for (int mt = 0; mt < 2; ++mt) {
            int row = m0 + wm * 32 + mt * 16 + (lane >> 2);
            float2 c0 = make_float2(acc[mt][nt][0] + bx, acc[mt][nt][1] + by);
            float2 c1 = make_float2(acc[mt][nt][2] + bx, acc[mt][nt][3] + by);
            *(float2*)&C[(size_t)row * N + col] = c0;
            *(float2*)&C[(size_t)(row + 8) * N + col] = c1;
        }
    }
}

// ============================================================================
// Recurrent layer (R11 skeleton): 128 CTAs x 256 threads. CTA: D[64 gates x
// 16 b], K=256 split across 2 warp-sets. W_hh = fp16 hi+lo in SMEM; h
// exchanged as SINGLE fp16 swizzled tile (8KB) -> flat cp.async. 4 mma/k16.
// SMEM: Whi [0,32K) | Wlo [32K,64K) | Bh [64K,72K) | gate bufs.
// ============================================================================
#define MO_AHI 0
#define MO_ALO 32768
#define MO_BHI 65536
#define MO_GB  (65536 + 8192)
#define GB_FLOATS 1152
#define LSTM_SMEM_MMA (MO_GB + 2*GB_FLOATS*4 + 64)

__device__ __forceinline__ unsigned aw_off(int row, int k) {
    return (unsigned)((k >> 6) * 8192) + sw_off(row, k & 63);
}
__device__ __forceinline__ unsigned bw_off(int row, int k) {
    return (unsigned)((k >> 6) * 2048) + sw_off(row, k & 63);
}

__global__ void __launch_bounds__(256, 1) lstm_mma(
    const float* __restrict__ xg, const float* __restrict__ whh,
    float* __restrict__ outh, float* __restrict__ outc)
{
    char* sm = (char*)s4;
    unsigned sb = (unsigned)__cvta_generic_to_shared(sm);
    float* gb0 = (float*)(sm + MO_GB);
    float* gb1 = gb0 + GB_FLOATS;

    const int tid  = threadIdx.x;
    const int lane = tid & 31;
    const int wid  = tid >> 5;              // 0..7
    const int ws   = wid & 3;               // m-tile set
    const int kh   = wid >> 2;              // K half (0/1)
    const int j0   = (blockIdx.x & 15) * 16;
    const int b0   = (blockIdx.x >> 4) * 16;

    // ---- stage W hi/lo (fp16) once: 64 rows x 256 k (32KB each) ----
    {
        int row = tid >> 2;                 // 0..63
        int kq  = (tid & 3) * 64;
        int wrow = (row >> 4) * HQ + j0 + (row & 15);
        const float4* wsrc = (const float4*)(whh + (size_t)wrow * HQ + kq);
#pragma unroll
        for (int q = 0; q < 16; ++q) {
            float4 v = wsrc[q];
            __half h0 = __float2half_rn(v.x), h1 = __float2half_rn(v.y);
            __half h2 = __float2half_rn(v.z), h3 = __float2half_rn(v.w);
            float l0 = v.x - __half2float(h0), l1 = v.y - __half2float(h1);
            float l2 = v.z - __half2float(h2), l3 = v.w - __half2float(h3);
            __half2 t0(h0, h1), t1(h2, h3);
            int k = kq + q * 4;
            unsigned oa = sb + MO_AHI + aw_off(row, k);
            stsv2(oa, *(unsigned*)&t0, *(unsigned*)&t1);
            stsv2(oa + (MO_ALO - MO_AHI), pk2h(l0, l1), pk2h(l2, l3));
        }
    }
    __syncthreads();

    // activation: 1 item/thread: jl = tid&15, b = tid>>4
    const int jl = tid & 15;
    const int bA = tid >> 4;
    float cst = 0.f;

    // ldsm addressing (per warp)
    const int arow = ws * 16 + (lane & 15);
    const int brow = lane & 15;
    const int klo  = ((lane >> 4) << 3) + kh * 128;

    // per-b-group barrier flags + h tiles
    const int bg = blockIdx.x >> 4;         // 0..7
    const int cg = blockIdx.x & 15;         // 0..15
    unsigned* myflag = &g_flags[(bg * 16 + cg) * FLAG_STRIDE];
    const unsigned* pollp = &g_flags[(bg * 16 + (lane & 15)) * FLAG_STRIDE];

    for (int t = 0; t < TQ; ++t) {
        const int rbuf = t & 1, wbuf = rbuf ^ 1;

        // prefetch xg_t (4 gates for our item)
        float xv[4];
        {
            const float* p = xg + (((size_t)(b0 + bA) * TQ + t) * GQ) + j0 + jl;
#pragma unroll
            for (int g = 0; g < 4; ++g) xv[g] = __ldcg(p + (g << 8));
        }

        // flat copy of the group's h tile (fp16, 8KB)
        {
            const char* srcb = &g_htile[rbuf][bg][0];
#pragma unroll
            for (int c = 0; c < 2; ++c) {
                int idx = tid + c * 256;
                cpasync16(sb + MO_BHI + idx * 16, srcb + idx * 16);
            }
            asm volatile("cp.async.commit_group;\n");
            asm volatile("cp.async.wait_group 0;\n");
        }
        __syncthreads();

        // D[64 x 16] partial (this warp-set's K half = 128): Wh*h + Wl*h
        float acc[2][4];
#pragma unroll
        for (int nt = 0; nt < 2; ++nt)
#pragma unroll
            for (int e = 0; e < 4; ++e) acc[nt][e] = 0.f;

#pragma unroll
        for (int k16 = 0; k16 < 128; k16 += 16) {
            int kk = k16 + klo;
            unsigned ka  = sb + MO_AHI + aw_off(arow, kk);
            unsigned kb2 = sb + MO_BHI + bw_off(brow, kk);
            unsigned ah[4], al[4], bh[4];
            ldsm4(ah, ka);
            ldsm4(al, ka + (MO_ALO - MO_AHI));
            ldsm4(bh, kb2);
            mma16816h(acc[0], ah, bh[0], bh[2]);
            mma16816h(acc[0], al, bh[0], bh[2]);
            mma16816h(acc[1], ah, bh[1], bh[3]);
            mma16816h(acc[1], al, bh[1], bh[3]);
        }

        // scatter partials to this K-half's gate buffer
        {
            float* gbk = kh ? gb1 : gb0;
            int rowA = ws * 16 + (lane >> 2);
            int c0   = 2 * (lane & 3);
#pragma unroll
            for (int nt = 0; nt < 2; ++nt) {
                *(float2*)&gbk[rowA * 18 + nt * 8 + c0]       = make_float2(acc[nt][0], acc[nt][1]);
                *(float2*)&gbk[(rowA + 8) * 18 + nt * 8 + c0] = make_float2(acc[nt][2], acc[nt][3]);
            }
        }
        __syncthreads();

        // activation + state update + publish exchange tile (fp16)
        float cn, hn;
        unsigned hiw = 0;
        {
            int b = bA;
            float pi = gb0[(jl     ) * 18 + b] + gb1[(jl     ) * 18 + b] + xv[0];
            float pf = gb0[(16 + jl) * 18 + b] + gb1[(16 + jl) * 18 + b] + xv[1];
            float pg = gb0[(32 + jl) * 18 + b] + gb1[(32 + jl) * 18 + b] + xv[2];
            float po = gb0[(48 + jl) * 18 + b] + gb1[(48 + jl) * 18 + b] + xv[3];
            float gi = sigf(pi), gf = sigf(pf), gg = tanhf_(pg), go = sigf(po);
            cn = gf * cst + gi * gg;
            cst = cn;
            hn = go * tanhf_(cn);

            __half hh = __float2half_rn(hn);
            unsigned pck = (unsigned)*(unsigned short*)&hh;
            unsigned pn  = __shfl_down_sync(0xFFFFFFFFu, pck, 1);

            if ((jl & 1) == 0) {
                hiw = pck | (pn << 16);          // {h16(j), h16(j+1)}
                char* baseh = &g_htile[wbuf][bg][0];
                *(unsigned*)(baseh + bw_off(bA, j0 + jl)) = hiw;
            }
        }

        // ---- per-b-group barrier release (exchange tile visible first) ----
        __syncthreads();
        if (tid == 0)
            asm volatile("st.release.gpu.global.u32 [%0], %1;"
                         :: "l"(myflag), "r"((unsigned)(t + 1)) : "memory");

        // deferred bookkeeping: overlaps peers' polling
        if ((jl & 1) == 0) {
            size_t hoff = ((size_t)(b0 + bA) * TQ + t) * HQ + j0 + jl;
            *(unsigned*)&g_a16[hoff] = hiw;
        }
        if (t == TQ - 1) {
            int bgl = b0 + bA, jg = j0 + jl;
            outh[bgl * HQ + jg] = hn;
            outc[bgl * HQ + jg] = cn;
        }

        if (wid == 0 && lane < 16) {
            unsigned v;
            do {
                asm volatile("ld.acquire.gpu.global.u32 %0, [%1];"
                             : "=r"(v) : "l"(pollp) : "memory");
            } while (v < (unsigned)(t + 1));
        }
        __syncthreads();
    }
}

// ---------------- launch -----------------------------------------------------
extern "C" void kernel_launch(void* const* d_in, const int* in_sizes, int n_in,
                              void* d_out, int out_size)
{
    const float* x    = (const float*)d_in[0];
    const float* wih0 = (const float*)d_in[1];
    const float* whh0 = (const float*)d_in[2];
    const float* bih0 = (const float*)d_in[3];
    const float* bhh0 = (const float*)d_in[4];
    const float* wih1 = (const float*)d_in[5];
    const float* whh1 = (const float*)d_in[6];
    const float* bih1 = (const float*)d_in[7];
    const float* bhh1 = (const float*)d_in[8];
    const float* wlin = (const float*)d_in[9];
    const float* blin = (const float*)d_in[10];

    float* out  = (float*)d_out;                    // [B,T,In]
    float* outh = out + (size_t)BQ * TQ * INQ;      // [2,B,H]
    float* outc = outh + 2 * BQ * HQ;               // [2,B,H]

    float* p_xg;
    __half *p_a16, *p_whi, *p_wlo;
    cudaGetSymbolAddress((void**)&p_xg,  g_xg);
    cudaGetSymbolAddress((void**)&p_a16, g_a16);
    cudaGetSymbolAddress((void**)&p_whi, g_whi);
    cudaGetSymbolAddress((void**)&p_wlo, g_wlo);
    cudaFuncSetAttribute(gemm_pp,  cudaFuncAttributeMaxDynamicSharedMemorySize, GEMM_SMEM);
    cudaFuncSetAttribute(lstm_mma, cudaFuncAttributeMaxDynamicSharedMemorySize, LSTM_SMEM_MMA);

    dim3 gg(GQ / 256, MROWS / 128);    // (4, 1024)
    dim3 gf(1, MROWS / 128);           // N=128 -> nsub=1

    const int CB = 256;
    int n4x = MROWS * INQ / 4;

    // ---- layer 0 ----
    cvt_a<<<(n4x + CB - 1) / CB, CB>>>((const float4*)x, (uint2*)p_a16, n4x);
    cvt_w<<<(GQ * INQ / 4 + CB - 1) / CB, CB>>>((const float4*)wih0, (uint2*)p_whi, (uint2*)p_wlo, GQ * INQ / 4);
    init_kernel<<<64, 256>>>();
    gemm_pp<<<gg, 256, GEMM_SMEM>>>(p_a16, p_whi, p_wlo, bih0, bhh0, p_xg, MROWS, GQ, INQ);
    lstm_mma<<<LGRID, 256, LSTM_SMEM_MMA>>>(p_xg, whh0, outh, outc);
    // lstm0 wrote h0seq as fp16 into g_a16

    // ---- layer 1 ----
    cvt_w<<<(GQ * HQ / 4 + CB - 1) / CB, CB>>>((const float4*)wih1, (uint2*)p_whi, (uint2*)p_wlo, GQ * HQ / 4);
    init_kernel<<<64, 256>>>();
    gemm_pp<<<gg, 256, GEMM_SMEM>>>(p_a16, p_whi, p_wlo, bih1, bhh1, p_xg, MROWS, GQ, HQ);
    lstm_mma<<<LGRID, 256, LSTM_SMEM_MMA>>>(p_xg, whh1, outh + BQ * HQ, outc + BQ * HQ);
    // lstm1 wrote h1seq as fp16 into g_a16

    // ---- final projection ----
    cvt_w<<<(INQ * HQ / 4 + CB - 1) / CB, CB>>>((const float4*)wlin, (uint2*)p_whi, (uint2*)p_wlo, INQ * HQ / 4);
    gemm_pp<<<gf, 256, GEMM_SMEM>>>(p_a16, p_whi, p_wlo, blin, nullptr, out, MROWS, INQ, HQ);
}

// round 15
// speedup vs baseline: 1.3590x; 1.0206x over previous
#include <cuda_runtime.h>
#include <cuda_fp16.h>
#include <cstdint>

#define BQ   128
#define TQ   1024
#define HQ   256
#define GQ   1024          // 4H
#define INQ  128
#define MROWS (BQ*TQ)      // 131072

// ---------------- scratch (device globals: no allocation allowed) ----------
__device__ __half g_xg16[(size_t)MROWS * GQ];     // 256 MB: input-gate preacts (fp16)
__device__ __half g_a16[(size_t)MROWS * HQ];      // 64 MB: A operand (fp16)
__device__ __half g_whi[GQ * HQ];                 // W hi (fp16)
__device__ __half g_wlo[GQ * HQ];                 // W lo (fp16)

// h exchange tiles: [buf][b-group]; 8KB used (swizzled fp16 B-tile)
__device__ __align__(16) char g_htile[2][8][16384];

#define LGRID 128
#define FLAG_STRIDE 32                               // 128B per flag
__device__ unsigned int g_flags[LGRID * FLAG_STRIDE];

extern __shared__ float4 s4[];

// ---------------- init: reset flags + h tile buf0 ----------------------------
__global__ void init_kernel() {
    int i = blockIdx.x * blockDim.x + threadIdx.x;
    int stride = gridDim.x * blockDim.x;
    for (int k = i; k < LGRID * FLAG_STRIDE; k += stride) g_flags[k] = 0u;
    unsigned* p = (unsigned*)&g_htile[0][0][0];
    for (int k = i; k < 8 * 16384 / 4; k += stride) p[k] = 0u;
}

// ---------------- helpers ----------------------------------------------------
__device__ __forceinline__ void mma16816h(float* d, const unsigned* a,
                                          unsigned b0, unsigned b1) {
    asm volatile(
        "mma.sync.aligned.m16n8k16.row.col.f32.f16.f16.f32 "
        "{%0,%1,%2,%3}, {%4,%5,%6,%7}, {%8,%9}, {%0,%1,%2,%3};\n"
        : "+f"(d[0]), "+f"(d[1]), "+f"(d[2]), "+f"(d[3])
        : "r"(a[0]), "r"(a[1]), "r"(a[2]), "r"(a[3]), "r"(b0), "r"(b1));
}

__device__ __forceinline__ void ldsm4(unsigned* r, unsigned addr) {
    asm volatile(
        "ldmatrix.sync.aligned.m8n8.x4.shared.b16 {%0,%1,%2,%3}, [%4];\n"
        : "=r"(r[0]), "=r"(r[1]), "=r"(r[2]), "=r"(r[3]) : "r"(addr));
}

// fp16 element (row, k) inside rows x 64k tile: 128B rows, 16B chunks xor row&7
__device__ __forceinline__ unsigned sw_off(int row, int k) {
    return (unsigned)(row * 128 + ((((k >> 3) ^ row) & 7) << 4) + ((k & 7) << 1));
}

__device__ __forceinline__ unsigned pk2h(float a, float b) {
    __half2 t(__float2half_rn(a), __float2half_rn(b));
    return *(unsigned*)&t;
}

__device__ __forceinline__ void stsv2(unsigned addr, unsigned a, unsigned b) {
    asm volatile("st.shared.v2.b32 [%0], {%1,%2};\n" :: "r"(addr), "r"(a), "r"(b));
}

__device__ __forceinline__ void cpasync16(unsigned dst, const void* src) {
    asm volatile("cp.async.cg.shared.global [%0], [%1], 16;\n" :: "r"(dst), "l"(src));
}

__device__ __forceinline__ float sigf(float x)   { return 1.f / (1.f + __expf(-x)); }
__device__ __forceinline__ float tanhf_(float x) { return 2.f / (1.f + __expf(-2.f * x)) - 1.f; }

// ---------------- converts (memory-bound passes) ------------------------------
__global__ void cvt_a(const float4* __restrict__ src, uint2* __restrict__ dst, int n4) {
    int i = blockIdx.x * blockDim.x + threadIdx.x;
    if (i >= n4) return;
    float4 v = src[i];
    dst[i] = make_uint2(pk2h(v.x, v.y), pk2h(v.z, v.w));
}
__global__ void cvt_w(const float4* __restrict__ src,
                      uint2* __restrict__ hi, uint2* __restrict__ lo, int n4) {
    int i = blockIdx.x * blockDim.x + threadIdx.x;
    if (i >= n4) return;
    float4 v = src[i];
    __half h0 = __float2half_rn(v.x), h1 = __float2half_rn(v.y);
    __half h2 = __float2half_rn(v.z), h3 = __float2half_rn(v.w);
    float l0 = v.x - __half2float(h0), l1 = v.y - __half2float(h1);
    float l2 = v.z - __half2float(h2), l3 = v.w - __half2float(h3);
    __half2 t0(h0, h1), t1(h2, h3);
    hi[i] = make_uint2(*(unsigned*)&t0, *(unsigned*)&t1);
    lo[i] = make_uint2(pk2h(l0, l1), pk2h(l2, l3));
}

// ============================================================================
// Double-buffered cp.async fp16 GEMM, CTA tile 128 x 256.
// C = A(MxK)*(Wh+Wl)(NxK)^T + b1 + b2.  A single fp16; W split hi/lo.
// half_out: 1 -> C is __half (xg), 0 -> C is float (final output).
// ============================================================================
#define GT 16384
#define STG_B  (5 * GT)
#define GEMM_SMEM (2 * STG_B)

__global__ void __launch_bounds__(256, 1) gemm_pp(
    const __half* __restrict__ A,
    const __half* __restrict__ Bhi, const __half* __restrict__ Blo,
    const float* __restrict__ b1, const float* __restrict__ b2,
    float* __restrict__ C, int M, int N, int K, int half_out)
{
    unsigned sbase = (unsigned)__cvta_generic_to_shared((char*)s4);

    const int tid  = threadIdx.x;
    const int lane = tid & 31;
    const int warp = tid >> 5;
    const int wm   = warp & 3;
    const int wn   = warp >> 2;
    const int m0   = blockIdx.y << 7;
    const int n0   = blockIdx.x << 8;
    const int nsub = (N - n0 >= 256) ? 2 : 1;

    const int lrow = tid >> 1;
    const int lc0  = (tid & 1) * 4;

    const __half* pA  = A   + (size_t)(m0 + lrow) * K;
    const __half* pBh = Bhi + (size_t)(n0 + lrow) * K;
    const __half* pBl = Blo + (size_t)(n0 + lrow) * K;

    float acc[2][16][4];
#pragma unroll
    for (int mt = 0; mt < 2; ++mt)
#pragma unroll
        for (int nt = 0; nt < 16; ++nt)
#pragma unroll
            for (int e = 0; e < 4; ++e) acc[mt][nt][e] = 0.f;

    const int nslab = K >> 6;

    auto issue = [&](int stage, int k0) {
        unsigned sb = sbase + stage * STG_B;
#pragma unroll
        for (int c = 0; c < 4; ++c) {
            int ko = (lc0 + c) << 3;
            unsigned d = sb + sw_off(lrow, ko);
            cpasync16(d,          pA  + k0 + ko);
            cpasync16(d + GT,     pBh + k0 + ko);
            cpasync16(d + 2 * GT, pBl + k0 + ko);
            if (nsub == 2) {
                cpasync16(d + 3 * GT, pBh + (size_t)128 * K + k0 + ko);
                cpasync16(d + 4 * GT, pBl + (size_t)128 * K + k0 + ko);
            }
        }
        asm volatile("cp.async.commit_group;\n");
    };

    issue(0, 0);

    for (int s = 0; s < nslab; ++s) {
        if (s + 1 < nslab) {
            issue((s + 1) & 1, (s + 1) << 6);
            asm volatile("cp.async.wait_group 1;\n");
        } else {
            asm volatile("cp.async.wait_group 0;\n");
        }
        __syncthreads();

        unsigned sb = sbase + (s & 1) * STG_B;
#pragma unroll
        for (int k16 = 0; k16 < 64; k16 += 16) {
            unsigned ah[2][4];
#pragma unroll
            for (int mt = 0; mt < 2; ++mt) {
                int row = wm * 32 + mt * 16 + (lane & 15);
                int kk  = k16 + ((lane >> 4) << 3);
                ldsm4(ah[mt], sb + sw_off(row, kk));
            }
#pragma unroll
            for (int sub = 0; sub < 2; ++sub) {
                if (sub >= nsub) break;
                unsigned bbase = sb + (1 + 2 * sub) * GT;
#pragma unroll
                for (int g = 0; g < 4; ++g) {
                    unsigned bh[4], bl[4];
                    int row = wn * 64 + g * 16 + (lane & 15);
                    int kk  = k16 + ((lane >> 4) << 3);
                    unsigned bd = bbase + sw_off(row, kk);
                    ldsm4(bh, bd);
                    ldsm4(bl, bd + GT);
                    int nb = sub * 8 + 2 * g;
#pragma unroll
                    for (int mt = 0; mt < 2; ++mt) {
                        mma16816h(acc[mt][nb],     ah[mt], bh[0], bh[2]);
                        mma16816h(acc[mt][nb],     ah[mt], bl[0], bl[2]);
                        mma16816h(acc[mt][nb + 1], ah[mt], bh[1], bh[3]);
                        mma16816h(acc[mt][nb + 1], ah[mt], bl[1], bl[3]);
                    }
                }
            }
        }
        __syncthreads();
    }

#pragma unroll
    for (int nt = 0; nt < 16; ++nt) {
        int sub = nt >> 3, ntl = nt & 7;
        if (sub >= nsub) break;
        int col = n0 + sub * 128 + wn * 64 + ntl * 8 + ((lane & 3) << 1);
        float bx = 0.f, by = 0.f;
        if (b1) { float2 t = *(const float2*)&b1[col]; bx += t.x; by += t.y; }
        if (b2) { float2 t = *(const float2*)&b2[col]; bx += t.x; by += t.y; }
#pragma unroll
        for (int mt = 0; mt < 2; ++mt) {
            int row = m0 + wm * 32 + mt * 16 + (lane >> 2);
            if (half_out) {
                __half* C16 = (__half*)C;
                *(unsigned*)&C16[(size_t)row * N + col] =
                    pk2h(acc[mt][nt][0] + bx, acc[mt][nt][1] + by);
                *(unsigned*)&C16[(size_t)(row + 8) * N + col] =
                    pk2h(acc[mt][nt][2] + bx, acc[mt][nt][3] + by);
            } else {
                *(float2*)&C[(size_t)row * N + col] =
                    make_float2(acc[mt][nt][0] + bx, acc[mt][nt][1] + by);
                *(float2*)&C[(size_t)(row + 8) * N + col] =
                    make_float2(acc[mt][nt][2] + bx, acc[mt][nt][3] + by);
            }
        }
    }
}

// ============================================================================
// Recurrent layer: 128 CTAs x 256 threads. CTA: D[64 gates x 16 b], K=256
// split across 2 warp-sets. W_hh fragments RESIDENT IN REGISTERS (loaded
// once via ldsm). h exchanged as fp16 swizzled tile (8KB) -> flat cp.async.
// xg (fp16) software-pipelined one step ahead.
// SMEM: Whi [0,32K) | Wlo [32K,64K) | Bh [64K,72K) | gate bufs.
// ============================================================================
#define MO_AHI 0
#define MO_ALO 32768
#define MO_BHI 65536
#define MO_GB  (65536 + 8192)
#define GB_FLOATS 1152
#define LSTM_SMEM_MMA (MO_GB + 2*GB_FLOATS*4 + 64)

__device__ __forceinline__ unsigned aw_off(int row, int k) {
    return (unsigned)((k >> 6) * 8192) + sw_off(row, k & 63);
}
__device__ __forceinline__ unsigned bw_off(int row, int k) {
    return (unsigned)((k >> 6) * 2048) + sw_off(row, k & 63);
}

__global__ void __launch_bounds__(256, 1) lstm_mma(
    const __half* __restrict__ xg, const float* __restrict__ whh,
    float* __restrict__ outh, float* __restrict__ outc)
{
    char* sm = (char*)s4;
    unsigned sb = (unsigned)__cvta_generic_to_shared(sm);
    float* gb0 = (float*)(sm + MO_GB);
    float* gb1 = gb0 + GB_FLOATS;

    const int tid  = threadIdx.x;
    const int lane = tid & 31;
    const int wid  = tid >> 5;              // 0..7
    const int ws   = wid & 3;               // m-tile set
    const int kh   = wid >> 2;              // K half (0/1)
    const int j0   = (blockIdx.x & 15) * 16;
    const int b0   = (blockIdx.x >> 4) * 16;

    // ---- stage W hi/lo (fp16) to SMEM once: 64 rows x 256 k (32KB each) ----
    {
        int row = tid >> 2;                 // 0..63
        int kq  = (tid & 3) * 64;
        int wrow = (row >> 4) * HQ + j0 + (row & 15);
        const float4* wsrc = (const float4*)(whh + (size_t)wrow * HQ + kq);
#pragma unroll
        for (int q = 0; q < 16; ++q) {
            float4 v = wsrc[q];
            __half h0 = __float2half_rn(v.x), h1 = __float2half_rn(v.y);
            __half h2 = __float2half_rn(v.z), h3 = __float2half_rn(v.w);
            float l0 = v.x - __half2float(h0), l1 = v.y - __half2float(h1);
            float l2 = v.z - __half2float(h2), l3 = v.w - __half2float(h3);
            __half2 t0(h0, h1), t1(h2, h3);
            int k = kq + q * 4;
            unsigned oa = sb + MO_AHI + aw_off(row, k);
            stsv2(oa, *(unsigned*)&t0, *(unsigned*)&t1);
            stsv2(oa + (MO_ALO - MO_AHI), pk2h(l0, l1), pk2h(l2, l3));
        }
    }
    __syncthreads();

    // ldsm addressing (per warp)
    const int arow = ws * 16 + (lane & 15);
    const int brow = lane & 15;
    const int klo  = ((lane >> 4) << 3) + kh * 128;

    // ---- hoist W fragments into registers (static across all timesteps) ----
    unsigned ahW[8][4], alW[8][4];
#pragma unroll
    for (int ii = 0; ii < 8; ++ii) {
        int kk = ii * 16 + klo;
        unsigned ka = sb + MO_AHI + aw_off(arow, kk);
        ldsm4(ahW[ii], ka);
        ldsm4(alW[ii], ka + (MO_ALO - MO_AHI));
    }

    // activation: 1 item/thread: jl = tid&15, b = tid>>4
    const int jl = tid & 15;
    const int bA = tid >> 4;
    float cst = 0.f;

    // per-b-group barrier flags + h tiles
    const int bg = blockIdx.x >> 4;         // 0..7
    const int cg = blockIdx.x & 15;         // 0..15
    unsigned* myflag = &g_flags[(bg * 16 + cg) * FLAG_STRIDE];
    const unsigned* pollp = &g_flags[(bg * 16 + (lane & 15)) * FLAG_STRIDE];

    // xg pipeline: prefetch t=0
    const __half* xbase = xg + (size_t)(b0 + bA) * TQ * GQ + j0 + jl;
    float xv[4];
#pragma unroll
    for (int g = 0; g < 4; ++g)
        xv[g] = __half2float(__ldcg(xbase + (g << 8)));

    for (int t = 0; t < TQ; ++t) {
        const int rbuf = t & 1, wbuf = rbuf ^ 1;

        // flat copy of the group's h tile (fp16, 8KB)
        {
            const char* srcb = &g_htile[rbuf][bg][0];
#pragma unroll
            for (int c = 0; c < 2; ++c) {
                int idx = tid + c * 256;
                cpasync16(sb + MO_BHI + idx * 16, srcb + idx * 16);
            }
            asm volatile("cp.async.commit_group;\n");
            asm volatile("cp.async.wait_group 0;\n");
        }
        __syncthreads();

        // D[64 x 16] partial (this warp-set's K half = 128): Wh*h + Wl*h
        float acc[2][4];
#pragma unroll
        for (int nt = 0; nt < 2; ++nt)
#pragma unroll
            for (int e = 0; e < 4; ++e) acc[nt][e] = 0.f;

#pragma unroll
        for (int ii = 0; ii < 8; ++ii) {
            int kk = ii * 16 + klo;
            unsigned bh[4];
            ldsm4(bh, sb + MO_BHI + bw_off(brow, kk));
            mma16816h(acc[0], ahW[ii], bh[0], bh[2]);
            mma16816h(acc[0], alW[ii], bh[0], bh[2]);
            mma16816h(acc[1], ahW[ii], bh[1], bh[3]);
            mma16816h(acc[1], alW[ii], bh[1], bh[3]);
        }

        // scatter partials to this K-half's gate buffer
        {
            float* gbk = kh ? gb1 : gb0;
            int rowA = ws * 16 + (lane >> 2);
            int c0   = 2 * (lane & 3);
#pragma unroll
            for (int nt = 0; nt < 2; ++nt) {
                *(float2*)&gbk[rowA * 18 + nt * 8 + c0]       = make_float2(acc[nt][0], acc[nt][1]);
                *(float2*)&gbk[(rowA + 8) * 18 + nt * 8 + c0] = make_float2(acc[nt][2], acc[nt][3]);
            }
        }

        // prefetch xg for t+1 (max latency cover)
        float xvn[4];
        if (t + 1 < TQ) {
            const __half* pn2 = xbase + (size_t)(t + 1) * GQ;
#pragma unroll
            for (int g = 0; g < 4; ++g)
                xvn[g] = __half2float(__ldcg(pn2 + (g << 8)));
        }
        __syncthreads();

        // activation + state update + publish exchange tile (fp16)
        float cn, hn;
        unsigned hiw = 0;
        {
            int b = bA;
            float pi = gb0[(jl     ) * 18 + b] + gb1[(jl     ) * 18 + b] + xv[0];
            float pf = gb0[(16 + jl) * 18 + b] + gb1[(16 + jl) * 18 + b] + xv[1];
            float pg = gb0[(32 + jl) * 18 + b] + gb1[(32 + jl) * 18 + b] + xv[2];
            float po = gb0[(48 + jl) * 18 + b] + gb1[(48 + jl) * 18 + b] + xv[3];
            float gi = sigf(pi), gf = sigf(pf), gg = tanhf_(pg), go = sigf(po);
            cn = gf * cst + gi * gg;
            cst = cn;
            hn = go * tanhf_(cn);

            __half hh = __float2half_rn(hn);
            unsigned pck = (unsigned)*(unsigned short*)&hh;
            unsigned pn  = __shfl_down_sync(0xFFFFFFFFu, pck, 1);

            if ((jl & 1) == 0) {
                hiw = pck | (pn << 16);          // {h16(j), h16(j+1)}
                char* baseh = &g_htile[wbuf][bg][0];
                *(unsigned*)(baseh + bw_off(bA, j0 + jl)) = hiw;
            }
        }

        // ---- per-b-group barrier release (exchange tile visible first) ----
        __syncthreads();
        if (tid == 0)
            asm volatile("st.release.gpu.global.u32 [%0], %1;"
                         :: "l"(myflag), "r"((unsigned)(t + 1)) : "memory");

        // deferred bookkeeping: overlaps peers' polling
        if ((jl & 1) == 0) {
            size_t hoff = ((size_t)(b0 + bA) * TQ + t) * HQ + j0 + jl;
            *(unsigned*)&g_a16[hoff] = hiw;
        }
        if (t == TQ - 1) {
            int bgl = b0 + bA, jg = j0 + jl;
            outh[bgl * HQ + jg] = hn;
            outc[bgl * HQ + jg] = cn;
        }

        if (wid == 0 && lane < 16) {
            unsigned v;
            do {
                asm volatile("ld.acquire.gpu.global.u32 %0, [%1];"
                             : "=r"(v) : "l"(pollp) : "memory");
            } while (v < (unsigned)(t + 1));
        }
        __syncthreads();

        xv[0] = xvn[0]; xv[1] = xvn[1]; xv[2] = xvn[2]; xv[3] = xvn[3];
    }
}

// ---------------- launch -----------------------------------------------------
extern "C" void kernel_launch(void* const* d_in, const int* in_sizes, int n_in,
                              void* d_out, int out_size)
{
    const float* x    = (const float*)d_in[0];
    const float* wih0 = (const float*)d_in[1];
    const float* whh0 = (const float*)d_in[2];
    const float* bih0 = (const float*)d_in[3];
    const float* bhh0 = (const float*)d_in[4];
    const float* wih1 = (const float*)d_in[5];
    const float* whh1 = (const float*)d_in[6];
    const float* bih1 = (const float*)d_in[7];
    const float* bhh1 = (const float*)d_in[8];
    const float* wlin = (const float*)d_in[9];
    const float* blin = (const float*)d_in[10];

    float* out  = (float*)d_out;                    // [B,T,In]
    float* outh = out + (size_t)BQ * TQ * INQ;      // [2,B,H]
    float* outc = outh + 2 * BQ * HQ;               // [2,B,H]

    __half *p_xg, *p_a16, *p_whi, *p_wlo;
    cudaGetSymbolAddress((void**)&p_xg,  g_xg16);
    cudaGetSymbolAddress((void**)&p_a16, g_a16);
    cudaGetSymbolAddress((void**)&p_whi, g_whi);
    cudaGetSymbolAddress((void**)&p_wlo, g_wlo);
    cudaFuncSetAttribute(gemm_pp,  cudaFuncAttributeMaxDynamicSharedMemorySize, GEMM_SMEM);
    cudaFuncSetAttribute(lstm_mma, cudaFuncAttributeMaxDynamicSharedMemorySize, LSTM_SMEM_MMA);

    dim3 gg(GQ / 256, MROWS / 128);    // (4, 1024)
    dim3 gf(1, MROWS / 128);           // N=128 -> nsub=1

    const int CB = 256;
    int n4x = MROWS * INQ / 4;

    // ---- layer 0 ----
    cvt_a<<<(n4x + CB - 1) / CB, CB>>>((const float4*)x, (uint2*)p_a16, n4x);
    cvt_w<<<(GQ * INQ / 4 + CB - 1) / CB, CB>>>((const float4*)wih0, (uint2*)p_whi, (uint2*)p_wlo, GQ * INQ / 4);
    init_kernel<<<64, 256>>>();
    gemm_pp<<<gg, 256, GEMM_SMEM>>>(p_a16, p_whi, p_wlo, bih0, bhh0, (float*)p_xg, MROWS, GQ, INQ, 1);
    lstm_mma<<<LGRID, 256, LSTM_SMEM_MMA>>>(p_xg, whh0, outh, outc);
    // lstm0 wrote h0seq as fp16 into g_a16

    // ---- layer 1 ----
    cvt_w<<<(GQ * HQ / 4 + CB - 1) / CB, CB>>>((const float4*)wih1, (uint2*)p_whi, (uint2*)p_wlo, GQ * HQ / 4);
    init_kernel<<<64, 256>>>();
    gemm_pp<<<gg, 256, GEMM_SMEM>>>(p_a16, p_whi, p_wlo, bih1, bhh1, (float*)p_xg, MROWS, GQ, HQ, 1);
    lstm_mma<<<LGRID, 256, LSTM_SMEM_MMA>>>(p_xg, whh1, outh + BQ * HQ, outc + BQ * HQ);
    // lstm1 wrote h1seq as fp16 into g_a16

    // ---- final projection (fp32 out) ----
    cvt_w<<<(INQ * HQ / 4 + CB - 1) / CB, CB>>>((const float4*)wlin, (uint2*)p_whi, (uint2*)p_wlo, INQ * HQ / 4);
    gemm_pp<<<gf, 256, GEMM_SMEM>>>(p_a16, p_whi, p_wlo, blin, nullptr, out, MROWS, INQ, HQ, 0);
}

// round 16
// speedup vs baseline: 1.5935x; 1.1725x over previous
#include <cuda_runtime.h>
#include <cuda_fp16.h>
#include <cstdint>

#define BQ   128
#define TQ   1024
#define HQ   256
#define GQ   1024          // 4H
#define INQ  128
#define MROWS (BQ*TQ)      // 131072

// ---------------- scratch (device globals: no allocation allowed) ----------
__device__ __half g_xg16[(size_t)MROWS * GQ];     // 256 MB: input-gate preacts (fp16)
__device__ __half g_a16[(size_t)MROWS * HQ];      // 64 MB: A operand (fp16)
__device__ __half g_whi[GQ * HQ];                 // W hi (fp16)
__device__ __half g_wlo[GQ * HQ];                 // W lo (fp16)

// h exchange tiles: [buf][b-group]; 8KB used (swizzled fp16 B-tile)
__device__ __align__(16) char g_htile[2][8][16384];

#define LGRID 128
#define FLAG_STRIDE 32                               // 128B per flag
__device__ unsigned int g_flags[LGRID * FLAG_STRIDE];

extern __shared__ float4 s4[];

// ---------------- init: reset flags + h tile buf0 ----------------------------
__global__ void init_kernel() {
    int i = blockIdx.x * blockDim.x + threadIdx.x;
    int stride = gridDim.x * blockDim.x;
    for (int k = i; k < LGRID * FLAG_STRIDE; k += stride) g_flags[k] = 0u;
    unsigned* p = (unsigned*)&g_htile[0][0][0];
    for (int k = i; k < 8 * 16384 / 4; k += stride) p[k] = 0u;
}

// ---------------- helpers ----------------------------------------------------
__device__ __forceinline__ void mma16816h(float* d, const unsigned* a,
                                          unsigned b0, unsigned b1) {
    asm volatile(
        "mma.sync.aligned.m16n8k16.row.col.f32.f16.f16.f32 "
        "{%0,%1,%2,%3}, {%4,%5,%6,%7}, {%8,%9}, {%0,%1,%2,%3};\n"
        : "+f"(d[0]), "+f"(d[1]), "+f"(d[2]), "+f"(d[3])
        : "r"(a[0]), "r"(a[1]), "r"(a[2]), "r"(a[3]), "r"(b0), "r"(b1));
}

__device__ __forceinline__ void ldsm4(unsigned* r, unsigned addr) {
    asm volatile(
        "ldmatrix.sync.aligned.m8n8.x4.shared.b16 {%0,%1,%2,%3}, [%4];\n"
        : "=r"(r[0]), "=r"(r[1]), "=r"(r[2]), "=r"(r[3]) : "r"(addr));
}

// fp16 element (row, k) inside rows x 64k tile: 128B rows, 16B chunks xor row&7
__device__ __forceinline__ unsigned sw_off(int row, int k) {
    return (unsigned)(row * 128 + ((((k >> 3) ^ row) & 7) << 4) + ((k & 7) << 1));
}

__device__ __forceinline__ unsigned pk2h(float a, float b) {
    __half2 t(__float2half_rn(a), __float2half_rn(b));
    return *(unsigned*)&t;
}

__device__ __forceinline__ void stsv2(unsigned addr, unsigned a, unsigned b) {
    asm volatile("st.shared.v2.b32 [%0], {%1,%2};\n" :: "r"(addr), "r"(a), "r"(b));
}

__device__ __forceinline__ void cpasync16(unsigned dst, const void* src) {
    asm volatile("cp.async.cg.shared.global [%0], [%1], 16;\n" :: "r"(dst), "l"(src));
}

// ---- MUFU-free activations: FMA-pipe exp + Newton reciprocal ----------------
__device__ __forceinline__ float exp_f(float x) {
    // r = rint(x*log2e) via +2^23 trick; f = x*log2e - r in [-0.5, 0.5]
    float t = fmaf(x, 1.4426950408889634f, 12582912.0f);
    float r = t - 12582912.0f;
    float f = fmaf(x, 1.4426950408889634f, -r);
    // 2^f: degree-5 Taylor in ln2*f (rel err ~3e-6)
    float p = 1.3333558e-3f;
    p = fmaf(p, f, 9.6181291e-3f);
    p = fmaf(p, f, 5.5504109e-2f);
    p = fmaf(p, f, 2.4022651e-1f);
    p = fmaf(p, f, 6.9314718e-1f);
    p = fmaf(p, f, 1.0f);
    return __int_as_float(__float_as_int(p) + (((int)r) << 23));
}
__device__ __forceinline__ float rcp_f(float d) {
    float r = __uint_as_float(0x7EF311C3u - __float_as_uint(d));
    r = r * fmaf(-d, r, 2.0f);
    r = r * fmaf(-d, r, 2.0f);
    r = r * fmaf(-d, r, 2.0f);
    return r;
}
__device__ __forceinline__ float sigf(float x) {
    return rcp_f(1.0f + exp_f(-x));
}
__device__ __forceinline__ float tanhf_(float x) {
    return fmaf(2.0f, rcp_f(1.0f + exp_f(-2.0f * x)), -1.0f);
}

// ---------------- converts (memory-bound passes) ------------------------------
__global__ void cvt_a(const float4* __restrict__ src, uint2* __restrict__ dst, int n4) {
    int i = blockIdx.x * blockDim.x + threadIdx.x;
    if (i >= n4) return;
    float4 v = src[i];
    dst[i] = make_uint2(pk2h(v.x, v.y), pk2h(v.z, v.w));
}
__global__ void cvt_w(const float4* __restrict__ src,
                      uint2* __restrict__ hi, uint2* __restrict__ lo, int n4) {
    int i = blockIdx.x * blockDim.x + threadIdx.x;
    if (i >= n4) return;
    float4 v = src[i];
    __half h0 = __float2half_rn(v.x), h1 = __float2half_rn(v.y);
    __half h2 = __float2half_rn(v.z), h3 = __float2half_rn(v.w);
    float l0 = v.x - __half2float(h0), l1 = v.y - __half2float(h1);
    float l2 = v.z - __half2float(h2), l3 = v.w - __half2float(h3);
    __half2 t0(h0, h1), t1(h2, h3);
    hi[i] = make_uint2(*(unsigned*)&t0, *(unsigned*)&t1);
    lo[i] = make_uint2(pk2h(l0, l1), pk2h(l2, l3));
}

// ============================================================================
// Double-buffered cp.async fp16 GEMM, CTA tile 128 x 256 (validated R14/15).
// C = A(MxK)*(Wh+Wl)(NxK)^T + b1 + b2.  A single fp16; W split hi/lo.
// half_out: 1 -> C is __half (xg), 0 -> C is float (final output).
// ============================================================================
#define GT 16384
#define STG_B  (5 * GT)
#define GEMM_SMEM (2 * STG_B)

__global__ void __launch_bounds__(256, 1) gemm_pp(
    const __half* __restrict__ A,
    const __half* __restrict__ Bhi, const __half* __restrict__ Blo,
    const float* __restrict__ b1, const float* __restrict__ b2,
    float* __restrict__ C, int M, int N, int K, int half_out)
{
    unsigned sbase = (unsigned)__cvta_generic_to_shared((char*)s4);

    const int tid  = threadIdx.x;
    const int lane = tid & 31;
    const int warp = tid >> 5;
    const int wm   = warp & 3;
    const int wn   = warp >> 2;
    const int m0   = blockIdx.y << 7;
    const int n0   = blockIdx.x << 8;
    const int nsub = (N - n0 >= 256) ? 2 : 1;

    const int lrow = tid >> 1;
    const int lc0  = (tid & 1) * 4;

    const __half* pA  = A   + (size_t)(m0 + lrow) * K;
    const __half* pBh = Bhi + (size_t)(n0 + lrow) * K;
    const __half* pBl = Blo + (size_t)(n0 + lrow) * K;

    float acc[2][16][4];
#pragma unroll
    for (int mt = 0; mt < 2; ++mt)
#pragma unroll
        for (int nt = 0; nt < 16; ++nt)
#pragma unroll
            for (int e = 0; e < 4; ++e) acc[mt][nt][e] = 0.f;

    const int nslab = K >> 6;

    auto issue = [&](int stage, int k0) {
        unsigned sb = sbase + stage * STG_B;
#pragma unroll
        for (int c = 0; c < 4; ++c) {
            int ko = (lc0 + c) << 3;
            unsigned d = sb + sw_off(lrow, ko);
            cpasync16(d,          pA  + k0 + ko);
            cpasync16(d + GT,     pBh + k0 + ko);
            cpasync16(d + 2 * GT, pBl + k0 + ko);
            if (nsub == 2) {
                cpasync16(d + 3 * GT, pBh + (size_t)128 * K + k0 + ko);
                cpasync16(d + 4 * GT, pBl + (size_t)128 * K + k0 + ko);
            }
        }
        asm volatile("cp.async.commit_group;\n");
    };

    issue(0, 0);

    for (int s = 0; s < nslab; ++s) {
        if (s + 1 < nslab) {
            issue((s + 1) & 1, (s + 1) << 6);
            asm volatile("cp.async.wait_group 1;\n");
        } else {
            asm volatile("cp.async.wait_group 0;\n");
        }
        __syncthreads();

        unsigned sb = sbase + (s & 1) * STG_B;
#pragma unroll
        for (int k16 = 0; k16 < 64; k16 += 16) {
            unsigned ah[2][4];
#pragma unroll
            for (int mt = 0; mt < 2; ++mt) {
                int row = wm * 32 + mt * 16 + (lane & 15);
                int kk  = k16 + ((lane >> 4) << 3);
                ldsm4(ah[mt], sb + sw_off(row, kk));
            }
#pragma unroll
            for (int sub = 0; sub < 2; ++sub) {
                if (sub >= nsub) break;
                unsigned bbase = sb + (1 + 2 * sub) * GT;
#pragma unroll
                for (int g = 0; g < 4; ++g) {
                    unsigned bh[4], bl[4];
                    int row = wn * 64 + g * 16 + (lane & 15);
                    int kk  = k16 + ((lane >> 4) << 3);
                    unsigned bd = bbase + sw_off(row, kk);
                    ldsm4(bh, bd);
                    ldsm4(bl, bd + GT);
                    int nb = sub * 8 + 2 * g;
#pragma unroll
                    for (int mt = 0; mt < 2; ++mt) {
                        mma16816h(acc[mt][nb],     ah[mt], bh[0], bh[2]);
                        mma16816h(acc[mt][nb],     ah[mt], bl[0], bl[2]);
                        mma16816h(acc[mt][nb + 1], ah[mt], bh[1], bh[3]);
                        mma16816h(acc[mt][nb + 1], ah[mt], bl[1], bl[3]);
                    }
                }
            }
        }
        __syncthreads();
    }

#pragma unroll
    for (int nt = 0; nt < 16; ++nt) {
        int sub = nt >> 3, ntl = nt & 7;
        if (sub >= nsub) break;
        int col = n0 + sub * 128 + wn * 64 + ntl * 8 + ((lane & 3) << 1);
        float bx = 0.f, by = 0.f;
        if (b1) { float2 t = *(const float2*)&b1[col]; bx += t.x; by += t.y; }
        if (b2) { float2 t = *(const float2*)&b2[col]; bx += t.x; by += t.y; }
#pragma unroll
        for (int mt = 0; mt < 2; ++mt) {
            int row = m0 + wm * 32 + mt * 16 + (lane >> 2);
            if (half_out) {
                __half* C16 = (__half*)C;
                *(unsigned*)&C16[(size_t)row * N + col] =
                    pk2h(acc[mt][nt][0] + bx, acc[mt][nt][1] + by);
                *(unsigned*)&C16[(size_t)(row + 8) * N + col] =
                    pk2h(acc[mt][nt][2] + bx, acc[mt][nt][3] + by);
            } else {
                *(float2*)&C[(size_t)row * N + col] =
                    make_float2(acc[mt][nt][0] + bx, acc[mt][nt][1] + by);
                *(float2*)&C[(size_t)(row + 8) * N + col] =
                    make_float2(acc[mt][nt][2] + bx, acc[mt][nt][3] + by);
            }
        }
    }
}

// ============================================================================
// Recurrent layer (R15 structure): 128 CTAs x 256 threads. CTA: D[64 gates x
// 16 b], K=256 split across 2 warp-sets. W fragments in registers; h tile
// via flat cp.async; xg pipelined; activations MUFU-free (FMA pipe).
// ============================================================================
#define MO_AHI 0
#define MO_ALO 32768
#define MO_BHI 65536
#define MO_GB  (65536 + 8192)
#define GB_FLOATS 1152
#define LSTM_SMEM_MMA (MO_GB + 2*GB_FLOATS*4 + 64)

__device__ __forceinline__ unsigned aw_off(int row, int k) {
    return (unsigned)((k >> 6) * 8192) + sw_off(row, k & 63);
}
__device__ __forceinline__ unsigned bw_off(int row, int k) {
    return (unsigned)((k >> 6) * 2048) + sw_off(row, k & 63);
}

__global__ void __launch_bounds__(256, 1) lstm_mma(
    const __half* __restrict__ xg, const float* __restrict__ whh,
    float* __restrict__ outh, float* __restrict__ outc)
{
    char* sm = (char*)s4;
    unsigned sb = (unsigned)__cvta_generic_to_shared(sm);
    float* gb0 = (float*)(sm + MO_GB);
    float* gb1 = gb0 + GB_FLOATS;

    const int tid  = threadIdx.x;
    const int lane = tid & 31;
    const int wid  = tid >> 5;              // 0..7
    const int ws   = wid & 3;               // m-tile set
    const int kh   = wid >> 2;              // K half (0/1)
    const int j0   = (blockIdx.x & 15) * 16;
    const int b0   = (blockIdx.x >> 4) * 16;

    // ---- stage W hi/lo (fp16) to SMEM once: 64 rows x 256 k (32KB each) ----
    {
        int row = tid >> 2;                 // 0..63
        int kq  = (tid & 3) * 64;
        int wrow = (row >> 4) * HQ + j0 + (row & 15);
        const float4* wsrc = (const float4*)(whh + (size_t)wrow * HQ + kq);
#pragma unroll
        for (int q = 0; q < 16; ++q) {
            float4 v = wsrc[q];
            __half h0 = __float2half_rn(v.x), h1 = __float2half_rn(v.y);
            __half h2 = __float2half_rn(v.z), h3 = __float2half_rn(v.w);
            float l0 = v.x - __half2float(h0), l1 = v.y - __half2float(h1);
            float l2 = v.z - __half2float(h2), l3 = v.w - __half2float(h3);
            __half2 t0(h0, h1), t1(h2, h3);
            int k = kq + q * 4;
            unsigned oa = sb + MO_AHI + aw_off(row, k);
            stsv2(oa, *(unsigned*)&t0, *(unsigned*)&t1);
            stsv2(oa + (MO_ALO - MO_AHI), pk2h(l0, l1), pk2h(l2, l3));
        }
    }
    __syncthreads();

    // ldsm addressing (per warp)
    const int arow = ws * 16 + (lane & 15);
    const int brow = lane & 15;
    const int klo  = ((lane >> 4) << 3) + kh * 128;

    // ---- hoist W fragments into registers (static across all timesteps) ----
    unsigned ahW[8][4], alW[8][4];
#pragma unroll
    for (int ii = 0; ii < 8; ++ii) {
        int kk = ii * 16 + klo;
        unsigned ka = sb + MO_AHI + aw_off(arow, kk);
        ldsm4(ahW[ii], ka);
        ldsm4(alW[ii], ka + (MO_ALO - MO_AHI));
    }

    // activation: 1 item/thread: jl = tid&15, b = tid>>4
    const int jl = tid & 15;
    const int bA = tid >> 4;
    float cst = 0.f;

    // per-b-group barrier flags + h tiles
    const int bg = blockIdx.x >> 4;         // 0..7
    const int cg = blockIdx.x & 15;         // 0..15
    unsigned* myflag = &g_flags[(bg * 16 + cg) * FLAG_STRIDE];
    const unsigned* pollp = &g_flags[(bg * 16 + (lane & 15)) * FLAG_STRIDE];

    // xg pipeline: prefetch t=0
    const __half* xbase = xg + (size_t)(b0 + bA) * TQ * GQ + j0 + jl;
    float xv[4];
#pragma unroll
    for (int g = 0; g < 4; ++g)
        xv[g] = __half2float(__ldcg(xbase + (g << 8)));

    for (int t = 0; t < TQ; ++t) {
        const int rbuf = t & 1, wbuf = rbuf ^ 1;

        // flat copy of the group's h tile (fp16, 8KB)
        {
            const char* srcb = &g_htile[rbuf][bg][0];
#pragma unroll
            for (int c = 0; c < 2; ++c) {
                int idx = tid + c * 256;
                cpasync16(sb + MO_BHI + idx * 16, srcb + idx * 16);
            }
            asm volatile("cp.async.commit_group;\n");
            asm volatile("cp.async.wait_group 0;\n");
        }
        __syncthreads();

        // D[64 x 16] partial (this warp-set's K half = 128): Wh*h + Wl*h
        float acc[2][4];
#pragma unroll
        for (int nt = 0; nt < 2; ++nt)
#pragma unroll
            for (int e = 0; e < 4; ++e) acc[nt][e] = 0.f;

#pragma unroll
        for (int ii = 0; ii < 8; ++ii) {
            int kk = ii * 16 + klo;
            unsigned bh[4];
            ldsm4(bh, sb + MO_BHI + bw_off(brow, kk));
            mma16816h(acc[0], ahW[ii], bh[0], bh[2]);
            mma16816h(acc[0], alW[ii], bh[0], bh[2]);
            mma16816h(acc[1], ahW[ii], bh[1], bh[3]);
            mma16816h(acc[1], alW[ii], bh[1], bh[3]);
        }

        // scatter partials to this K-half's gate buffer
        {
            float* gbk = kh ? gb1 : gb0;
            int rowA = ws * 16 + (lane >> 2);
            int c0   = 2 * (lane & 3);
#pragma unroll
            for (int nt = 0; nt < 2; ++nt) {
                *(float2*)&gbk[rowA * 18 + nt * 8 + c0]       = make_float2(acc[nt][0], acc[nt][1]);
                *(float2*)&gbk[(rowA + 8) * 18 + nt * 8 + c0] = make_float2(acc[nt][2], acc[nt][3]);
            }
        }

        // prefetch xg for t+1 (max latency cover)
        float xvn[4];
        if (t + 1 < TQ) {
            const __half* pn2 = xbase + (size_t)(t + 1) * GQ;
#pragma unroll
            for (int g = 0; g < 4; ++g)
                xvn[g] = __half2float(__ldcg(pn2 + (g << 8)));
        }
        __syncthreads();

        // activation + state update + publish exchange tile (fp16)
        float cn, hn;
        unsigned hiw = 0;
        {
            int b = bA;
            float pi = gb0[(jl     ) * 18 + b] + gb1[(jl     ) * 18 + b] + xv[0];
            float pf = gb0[(16 + jl) * 18 + b] + gb1[(16 + jl) * 18 + b] + xv[1];
            float pg = gb0[(32 + jl) * 18 + b] + gb1[(32 + jl) * 18 + b] + xv[2];
            float po = gb0[(48 + jl) * 18 + b] + gb1[(48 + jl) * 18 + b] + xv[3];
            float gi = sigf(pi), gf = sigf(pf), gg = tanhf_(pg), go = sigf(po);
            cn = gf * cst + gi * gg;
            cst = cn;
            hn = go * tanhf_(cn);

            __half hh = __float2half_rn(hn);
            unsigned pck = (unsigned)*(unsigned short*)&hh;
            unsigned pn  = __shfl_down_sync(0xFFFFFFFFu, pck, 1);

            if ((jl & 1) == 0) {
                hiw = pck | (pn << 16);          // {h16(j), h16(j+1)}
                char* baseh = &g_htile[wbuf][bg][0];
                *(unsigned*)(baseh + bw_off(bA, j0 + jl)) = hiw;
            }
        }

        // ---- per-b-group barrier release (exchange tile visible first) ----
        __syncthreads();
        if (tid == 0)
            asm volatile("st.release.gpu.global.u32 [%0], %1;"
                         :: "l"(myflag), "r"((unsigned)(t + 1)) : "memory");

        // deferred bookkeeping: overlaps peers' polling
        if ((jl & 1) == 0) {
            size_t hoff = ((size_t)(b0 + bA) * TQ + t) * HQ + j0 + jl;
            *(unsigned*)&g_a16[hoff] = hiw;
        }
        if (t == TQ - 1) {
            int bgl = b0 + bA, jg = j0 + jl;
            outh[bgl * HQ + jg] = hn;
            outc[bgl * HQ + jg] = cn;
        }

        if (wid == 0 && lane < 16) {
            unsigned v;
            do {
                asm volatile("ld.acquire.gpu.global.u32 %0, [%1];"
                             : "=r"(v) : "l"(pollp) : "memory");
            } while (v < (unsigned)(t + 1));
        }
        __syncthreads();

        xv[0] = xvn[0]; xv[1] = xvn[1]; xv[2] = xvn[2]; xv[3] = xvn[3];
    }
}

// ---------------- launch -----------------------------------------------------
extern "C" void kernel_launch(void* const* d_in, const int* in_sizes, int n_in,
                              void* d_out, int out_size)
{
    const float* x    = (const float*)d_in[0];
    const float* wih0 = (const float*)d_in[1];
    const float* whh0 = (const float*)d_in[2];
    const float* bih0 = (const float*)d_in[3];
    const float* bhh0 = (const float*)d_in[4];
    const float* wih1 = (const float*)d_in[5];
    const float* whh1 = (const float*)d_in[6];
    const float* bih1 = (const float*)d_in[7];
    const float* bhh1 = (const float*)d_in[8];
    const float* wlin = (const float*)d_in[9];
    const float* blin = (const float*)d_in[10];

    float* out  = (float*)d_out;                    // [B,T,In]
    float* outh = out + (size_t)BQ * TQ * INQ;      // [2,B,H]
    float* outc = outh + 2 * BQ * HQ;               // [2,B,H]

    __half *p_xg, *p_a16, *p_whi, *p_wlo;
    cudaGetSymbolAddress((void**)&p_xg,  g_xg16);
    cudaGetSymbolAddress((void**)&p_a16, g_a16);
    cudaGetSymbolAddress((void**)&p_whi, g_whi);
    cudaGetSymbolAddress((void**)&p_wlo, g_wlo);
    cudaFuncSetAttribute(gemm_pp,  cudaFuncAttributeMaxDynamicSharedMemorySize, GEMM_SMEM);
    cudaFuncSetAttribute(lstm_mma, cudaFuncAttributeMaxDynamicSharedMemorySize, LSTM_SMEM_MMA);

    dim3 gg(GQ / 256, MROWS / 128);    // (4, 1024)
    dim3 gf(1, MROWS / 128);           // N=128 -> nsub=1

    const int CB = 256;
    int n4x = MROWS * INQ / 4;

    // ---- layer 0 ----
    cvt_a<<<(n4x + CB - 1) / CB, CB>>>((const float4*)x, (uint2*)p_a16, n4x);
    cvt_w<<<(GQ * INQ / 4 + CB - 1) / CB, CB>>>((const float4*)wih0, (uint2*)p_whi, (uint2*)p_wlo, GQ * INQ / 4);
    init_kernel<<<64, 256>>>();
    gemm_pp<<<gg, 256, GEMM_SMEM>>>(p_a16, p_whi, p_wlo, bih0, bhh0, (float*)p_xg, MROWS, GQ, INQ, 1);
    lstm_mma<<<LGRID, 256, LSTM_SMEM_MMA>>>(p_xg, whh0, outh, outc);
    // lstm0 wrote h0seq as fp16 into g_a16

    // ---- layer 1 ----
    cvt_w<<<(GQ * HQ / 4 + CB - 1) / CB, CB>>>((const float4*)wih1, (uint2*)p_whi, (uint2*)p_wlo, GQ * HQ / 4);
    init_kernel<<<64, 256>>>();
    gemm_pp<<<gg, 256, GEMM_SMEM>>>(p_a16, p_whi, p_wlo, bih1, bhh1, (float*)p_xg, MROWS, GQ, HQ, 1);
    lstm_mma<<<LGRID, 256, LSTM_SMEM_MMA>>>(p_xg, whh1, outh + BQ * HQ, outc + BQ * HQ);
    // lstm1 wrote h1seq as fp16 into g_a16

    // ---- final projection (fp32 out) ----
    cvt_w<<<(INQ * HQ / 4 + CB - 1) / CB, CB>>>((const float4*)wlin, (uint2*)p_whi, (uint2*)p_wlo, INQ * HQ / 4);
    gemm_pp<<<gf, 256, GEMM_SMEM>>>(p_a16, p_whi, p_wlo, blin, nullptr, out, MROWS, INQ, HQ, 0);
}

// round 17
// speedup vs baseline: 1.8025x; 1.1312x over previous
#include <cuda_runtime.h>
#include <cuda_fp16.h>
#include <cstdint>

#define BQ   128
#define TQ   1024
#define HQ   256
#define GQ   1024          // 4H
#define INQ  128
#define MROWS (BQ*TQ)      // 131072

// ---------------- scratch (device globals: no allocation allowed) ----------
__device__ __half g_xg16[(size_t)MROWS * GQ];     // 256 MB: layer0 input preacts (fp16)
__device__ __half g_a16[(size_t)MROWS * HQ];      // 64 MB: GEMM A operand / h1seq (fp16)
__device__ __half g_whi[GQ * HQ];                 // W hi (fp16)
__device__ __half g_wlo[GQ * HQ];                 // W lo (fp16)

// h exchange tiles: [buf][b-group] = 16KB: {h0 swizzled 8KB | h1 swizzled 8KB}
__device__ __align__(16) char g_htile[2][8][16384];

#define LGRID 128
#define FLAG_STRIDE 32                               // 128B per flag
__device__ unsigned int g_flags[LGRID * FLAG_STRIDE];

extern __shared__ float4 s4[];

// ---------------- init: reset flags + BOTH h tile buffers --------------------
__global__ void init_kernel() {
    int i = blockIdx.x * blockDim.x + threadIdx.x;
    int stride = gridDim.x * blockDim.x;
    for (int k = i; k < LGRID * FLAG_STRIDE; k += stride) g_flags[k] = 0u;
    unsigned* p = (unsigned*)&g_htile[0][0][0];
    for (int k = i; k < 2 * 8 * 16384 / 4; k += stride) p[k] = 0u;
}

// ---------------- helpers ----------------------------------------------------
__device__ __forceinline__ void mma16816h(float* d, const unsigned* a,
                                          unsigned b0, unsigned b1) {
    asm volatile(
        "mma.sync.aligned.m16n8k16.row.col.f32.f16.f16.f32 "
        "{%0,%1,%2,%3}, {%4,%5,%6,%7}, {%8,%9}, {%0,%1,%2,%3};\n"
        : "+f"(d[0]), "+f"(d[1]), "+f"(d[2]), "+f"(d[3])
        : "r"(a[0]), "r"(a[1]), "r"(a[2]), "r"(a[3]), "r"(b0), "r"(b1));
}

__device__ __forceinline__ void ldsm4(unsigned* r, unsigned addr) {
    asm volatile(
        "ldmatrix.sync.aligned.m8n8.x4.shared.b16 {%0,%1,%2,%3}, [%4];\n"
        : "=r"(r[0]), "=r"(r[1]), "=r"(r[2]), "=r"(r[3]) : "r"(addr));
}

// fp16 element (row, k) inside rows x 64k tile: 128B rows, 16B chunks xor row&7
__device__ __forceinline__ unsigned sw_off(int row, int k) {
    return (unsigned)(row * 128 + ((((k >> 3) ^ row) & 7) << 4) + ((k & 7) << 1));
}

__device__ __forceinline__ unsigned pk2h(float a, float b) {
    __half2 t(__float2half_rn(a), __float2half_rn(b));
    return *(unsigned*)&t;
}

__device__ __forceinline__ void stsv2(unsigned addr, unsigned a, unsigned b) {
    asm volatile("st.shared.v2.b32 [%0], {%1,%2};\n" :: "r"(addr), "r"(a), "r"(b));
}

__device__ __forceinline__ void cpasync16(unsigned dst, const void* src) {
    asm volatile("cp.async.cg.shared.global [%0], [%1], 16;\n" :: "r"(dst), "l"(src));
}

// ---- MUFU-free activations (validated R16) ----------------------------------
__device__ __forceinline__ float exp_f(float x) {
    float t = fmaf(x, 1.4426950408889634f, 12582912.0f);
    float r = t - 12582912.0f;
    float f = fmaf(x, 1.4426950408889634f, -r);
    float p = 1.3333558e-3f;
    p = fmaf(p, f, 9.6181291e-3f);
    p = fmaf(p, f, 5.5504109e-2f);
    p = fmaf(p, f, 2.4022651e-1f);
    p = fmaf(p, f, 6.9314718e-1f);
    p = fmaf(p, f, 1.0f);
    return __int_as_float(__float_as_int(p) + (((int)r) << 23));
}
__device__ __forceinline__ float rcp_f(float d) {
    float r = __uint_as_float(0x7EF311C3u - __float_as_uint(d));
    r = r * fmaf(-d, r, 2.0f);
    r = r * fmaf(-d, r, 2.0f);
    r = r * fmaf(-d, r, 2.0f);
    return r;
}
__device__ __forceinline__ float sigf(float x)   { return rcp_f(1.0f + exp_f(-x)); }
__device__ __forceinline__ float tanhf_(float x) { return fmaf(2.0f, rcp_f(1.0f + exp_f(-2.0f * x)), -1.0f); }

// ---------------- converts (memory-bound passes) ------------------------------
__global__ void cvt_a(const float4* __restrict__ src, uint2* __restrict__ dst, int n4) {
    int i = blockIdx.x * blockDim.x + threadIdx.x;
    if (i >= n4) return;
    float4 v = src[i];
    dst[i] = make_uint2(pk2h(v.x, v.y), pk2h(v.z, v.w));
}
__global__ void cvt_w(const float4* __restrict__ src,
                      uint2* __restrict__ hi, uint2* __restrict__ lo, int n4) {
    int i = blockIdx.x * blockDim.x + threadIdx.x;
    if (i >= n4) return;
    float4 v = src[i];
    __half h0 = __float2half_rn(v.x), h1 = __float2half_rn(v.y);
    __half h2 = __float2half_rn(v.z), h3 = __float2half_rn(v.w);
    float l0 = v.x - __half2float(h0), l1 = v.y - __half2float(h1);
    float l2 = v.z - __half2float(h2), l3 = v.w - __half2float(h3);
    __half2 t0(h0, h1), t1(h2, h3);
    hi[i] = make_uint2(*(unsigned*)&t0, *(unsigned*)&t1);
    lo[i] = make_uint2(pk2h(l0, l1), pk2h(l2, l3));
}

// ============================================================================
// Double-buffered cp.async fp16 GEMM, CTA tile 128 x 256 (validated R14-16).
// ============================================================================
#define GT 16384
#define STG_B  (5 * GT)
#define GEMM_SMEM (2 * STG_B)

__global__ void __launch_bounds__(256, 1) gemm_pp(
    const __half* __restrict__ A,
    const __half* __restrict__ Bhi, const __half* __restrict__ Blo,
    const float* __restrict__ b1, const float* __restrict__ b2,
    float* __restrict__ C, int M, int N, int K, int half_out)
{
    unsigned sbase = (unsigned)__cvta_generic_to_shared((char*)s4);

    const int tid  = threadIdx.x;
    const int lane = tid & 31;
    const int warp = tid >> 5;
    const int wm   = warp & 3;
    const int wn   = warp >> 2;
    const int m0   = blockIdx.y << 7;
    const int n0   = blockIdx.x << 8;
    const int nsub = (N - n0 >= 256) ? 2 : 1;

    const int lrow = tid >> 1;
    const int lc0  = (tid & 1) * 4;

    const __half* pA  = A   + (size_t)(m0 + lrow) * K;
    const __half* pBh = Bhi + (size_t)(n0 + lrow) * K;
    const __half* pBl = Blo + (size_t)(n0 + lrow) * K;

    float acc[2][16][4];
#pragma unroll
    for (int mt = 0; mt < 2; ++mt)
#pragma unroll
        for (int nt = 0; nt < 16; ++nt)
#pragma unroll
            for (int e = 0; e < 4; ++e) acc[mt][nt][e] = 0.f;

    const int nslab = K >> 6;

    auto issue = [&](int stage, int k0) {
        unsigned sb = sbase + stage * STG_B;
#pragma unroll
        for (int c = 0; c < 4; ++c) {
            int ko = (lc0 + c) << 3;
            unsigned d = sb + sw_off(lrow, ko);
            cpasync16(d,          pA  + k0 + ko);
            cpasync16(d + GT,     pBh + k0 + ko);
            cpasync16(d + 2 * GT, pBl + k0 + ko);
            if (nsub == 2) {
                cpasync16(d + 3 * GT, pBh + (size_t)128 * K + k0 + ko);
                cpasync16(d + 4 * GT, pBl + (size_t)128 * K + k0 + ko);
            }
        }
        asm volatile("cp.async.commit_group;\n");
    };

    issue(0, 0);

    for (int s = 0; s < nslab; ++s) {
        if (s + 1 < nslab) {
            issue((s + 1) & 1, (s + 1) << 6);
            asm volatile("cp.async.wait_group 1;\n");
        } else {
            asm volatile("cp.async.wait_group 0;\n");
        }
        __syncthreads();

        unsigned sb = sbase + (s & 1) * STG_B;
#pragma unroll
        for (int k16 = 0; k16 < 64; k16 += 16) {
            unsigned ah[2][4];
#pragma unroll
            for (int mt = 0; mt < 2; ++mt) {
                int row = wm * 32 + mt * 16 + (lane & 15);
                int kk  = k16 + ((lane >> 4) << 3);
                ldsm4(ah[mt], sb + sw_off(row, kk));
            }
#pragma unroll
            for (int sub = 0; sub < 2; ++sub) {
                if (sub >= nsub) break;
                unsigned bbase = sb + (1 + 2 * sub) * GT;
#pragma unroll
                for (int g = 0; g < 4; ++g) {
                    unsigned bh[4], bl[4];
                    int row = wn * 64 + g * 16 + (lane & 15);
                    int kk  = k16 + ((lane >> 4) << 3);
                    unsigned bd = bbase + sw_off(row, kk);
                    ldsm4(bh, bd);
                    ldsm4(bl, bd + GT);
                    int nb = sub * 8 + 2 * g;
#pragma unroll
                    for (int mt = 0; mt < 2; ++mt) {
                        mma16816h(acc[mt][nb],     ah[mt], bh[0], bh[2]);
                        mma16816h(acc[mt][nb],     ah[mt], bl[0], bl[2]);
                        mma16816h(acc[mt][nb + 1], ah[mt], bh[1], bh[3]);
                        mma16816h(acc[mt][nb + 1], ah[mt], bl[1], bl[3]);
                    }
                }
            }
        }
        __syncthreads();
    }

#pragma unroll
    for (int nt = 0; nt < 16; ++nt) {
        int sub = nt >> 3, ntl = nt & 7;
        if (sub >= nsub) break;
        int col = n0 + sub * 128 + wn * 64 + ntl * 8 + ((lane & 3) << 1);
        float bx = 0.f, by = 0.f;
        if (b1) { float2 t = *(const float2*)&b1[col]; bx += t.x; by += t.y; }
        if (b2) { float2 t = *(const float2*)&b2[col]; bx += t.x; by += t.y; }
#pragma unroll
        for (int mt = 0; mt < 2; ++mt) {
            int row = m0 + wm * 32 + mt * 16 + (lane >> 2);
            if (half_out) {
                __half* C16 = (__half*)C;
                *(unsigned*)&C16[(size_t)row * N + col] =
                    pk2h(acc[mt][nt][0] + bx, acc[mt][nt][1] + by);
                *(unsigned*)&C16[(size_t)(row + 8) * N + col] =
                    pk2h(acc[mt][nt][2] + bx, acc[mt][nt][3] + by);
            } else {
                *(float2*)&C[(size_t)row * N + col] =
                    make_float2(acc[mt][nt][0] + bx, acc[mt][nt][1] + by);
                *(float2*)&C[(size_t)(row + 8) * N + col] =
                    make_float2(acc[mt][nt][2] + bx, acc[mt][nt][3] + by);
            }
        }
    }
}

// ============================================================================
// FUSED 2-layer recurrence, wavefront (layer1 lags layer0 by one step).
// 128 CTAs x 256 threads, 1025 global steps. CTA = j-chunk (16 j) x b-group
// (16 b) for BOTH layers:
//   L0: gates0 = Whh0(hi/lo fp16) . h0_{s-1}            (K=256)
//   L1: gates1 = Wih1(fp16) . h0_{s-1} + Whh1(hi/lo) . h1_{s-1}  (K=512)
// Exchange: {h0|h1} 16KB per group, flat cp.async. Barrier: distrib flags.
// SMEM: W0H|W0L|W1I|W1H|W1L (5x32KB) | Bh0 8KB | Bh1 8KB | 4 gate bufs.
// ============================================================================
#define MO_W0H 0
#define MO_W0L 32768
#define MO_W1I 65536
#define MO_W1H 98304
#define MO_W1L 131072
#define MO_BH0 163840
#define MO_BH1 172032
#define MO_GB  180224
#define GB_FLOATS 1152
#define LSTM_SMEM_F (MO_GB + 4*GB_FLOATS*4 + 64)

__device__ __forceinline__ unsigned aw_off(int row, int k) {
    return (unsigned)((k >> 6) * 8192) + sw_off(row, k & 63);
}
__device__ __forceinline__ unsigned bw_off(int row, int k) {
    return (unsigned)((k >> 6) * 2048) + sw_off(row, k & 63);
}

__global__ void __launch_bounds__(256, 1) lstm_fused(
    const __half* __restrict__ xg, const float* __restrict__ whh0,
    const float* __restrict__ wih1, const float* __restrict__ whh1,
    const float* __restrict__ bih1, const float* __restrict__ bhh1,
    float* __restrict__ outh, float* __restrict__ outc)
{
    char* sm = (char*)s4;
    unsigned sb = (unsigned)__cvta_generic_to_shared(sm);
    float* gb0 = (float*)(sm + MO_GB);
    float* gb1 = gb0 + GB_FLOATS;
    float* gb2 = gb1 + GB_FLOATS;
    float* gb3 = gb2 + GB_FLOATS;

    const int tid  = threadIdx.x;
    const int lane = tid & 31;
    const int wid  = tid >> 5;
    const int ws   = wid & 3;
    const int kh   = wid >> 2;              // K half (0/1)
    const int j0   = (blockIdx.x & 15) * 16;
    const int b0   = (blockIdx.x >> 4) * 16;

    // ---- stage the 5 W chunks (64 rows x 256 k each) ----
    {
        int row = tid >> 2;
        int kq  = (tid & 3) * 64;
        int wrow = (row >> 4) * HQ + j0 + (row & 15);
        const float4* s0 = (const float4*)(whh0 + (size_t)wrow * HQ + kq);
        const float4* s1 = (const float4*)(wih1 + (size_t)wrow * HQ + kq);
        const float4* s2 = (const float4*)(whh1 + (size_t)wrow * HQ + kq);
#pragma unroll
        for (int q = 0; q < 16; ++q) {
            int k = kq + q * 4;
            unsigned oa = aw_off(row, k);
            {   // Whh0 hi/lo
                float4 v = s0[q];
                __half h0 = __float2half_rn(v.x), h1 = __float2half_rn(v.y);
                __half h2 = __float2half_rn(v.z), h3 = __float2half_rn(v.w);
                __half2 t0(h0, h1), t1(h2, h3);
                stsv2(sb + MO_W0H + oa, *(unsigned*)&t0, *(unsigned*)&t1);
                stsv2(sb + MO_W0L + oa,
                      pk2h(v.x - __half2float(h0), v.y - __half2float(h1)),
                      pk2h(v.z - __half2float(h2), v.w - __half2float(h3)));
            }
            {   // Wih1 single
                float4 v = s1[q];
                stsv2(sb + MO_W1I + oa, pk2h(v.x, v.y), pk2h(v.z, v.w));
            }
            {   // Whh1 hi/lo
                float4 v = s2[q];
                __half h0 = __float2half_rn(v.x), h1 = __float2half_rn(v.y);
                __half h2 = __float2half_rn(v.z), h3 = __float2half_rn(v.w);
                __half2 t0(h0, h1), t1(h2, h3);
                stsv2(sb + MO_W1H + oa, *(unsigned*)&t0, *(unsigned*)&t1);
                stsv2(sb + MO_W1L + oa,
                      pk2h(v.x - __half2float(h0), v.y - __half2float(h1)),
                      pk2h(v.z - __half2float(h2), v.w - __half2float(h3)));
            }
        }
    }
    __syncthreads();

    // ldsm addressing (per warp)
    const int arow = ws * 16 + (lane & 15);
    const int brow = lane & 15;
    const int klo  = ((lane >> 4) << 3) + kh * 128;

    // activation item: jl = tid&15, b = tid>>4
    const int jl = tid & 15;
    const int bA = tid >> 4;
    const int jg = j0 + jl;
    float cst0 = 0.f, cst1 = 0.f;

    // layer-1 biases (per item, 4 gates)
    float bias1[4];
#pragma unroll
    for (int g = 0; g < 4; ++g)
        bias1[g] = bih1[g * HQ + jg] + bhh1[g * HQ + jg];

    // per-b-group barrier flags
    const int bg = blockIdx.x >> 4;
    const int cg = blockIdx.x & 15;
    unsigned* myflag = &g_flags[(bg * 16 + cg) * FLAG_STRIDE];
    const unsigned* pollp = &g_flags[(bg * 16 + (lane & 15)) * FLAG_STRIDE];

    // xg pipeline: prefetch s=0
    const __half* xbase = xg + (size_t)(b0 + bA) * TQ * GQ + jg;
    float xv[4];
#pragma unroll
    for (int g = 0; g < 4; ++g)
        xv[g] = __half2float(__ldcg(xbase + (g << 8)));

    for (int s = 0; s <= TQ; ++s) {
        const int rbuf = s & 1, wbuf = rbuf ^ 1;

        // flat copy of the group's {h0|h1} tiles (16KB)
        {
            const char* srcb = &g_htile[rbuf][bg][0];
#pragma unroll
            for (int c = 0; c < 4; ++c) {
                int idx = tid + c * 256;
                cpasync16(sb + MO_BH0 + idx * 16, srcb + idx * 16);
            }
            asm volatile("cp.async.commit_group;\n");
            asm volatile("cp.async.wait_group 0;\n");
        }
        __syncthreads();

        // ---- L0 mma (s < TQ): gates0 partial, K-half ----
        if (s < TQ) {
            float acc[2][4];
#pragma unroll
            for (int nt = 0; nt < 2; ++nt)
#pragma unroll
                for (int e = 0; e < 4; ++e) acc[nt][e] = 0.f;
#pragma unroll
            for (int ii = 0; ii < 8; ++ii) {
                int kk = ii * 16 + klo;
                unsigned bh[4], ah[4], al[4];
                ldsm4(bh, sb + MO_BH0 + bw_off(brow, kk));
                unsigned ka = aw_off(arow, kk);
                ldsm4(ah, sb + MO_W0H + ka);
                ldsm4(al, sb + MO_W0L + ka);
                mma16816h(acc[0], ah, bh[0], bh[2]);
                mma16816h(acc[0], al, bh[0], bh[2]);
                mma16816h(acc[1], ah, bh[1], bh[3]);
                mma16816h(acc[1], al, bh[1], bh[3]);
            }
            float* gbk = kh ? gb1 : gb0;
            int rowA = ws * 16 + (lane >> 2);
            int c0   = 2 * (lane & 3);
#pragma unroll
            for (int nt = 0; nt < 2; ++nt) {
                *(float2*)&gbk[rowA * 18 + nt * 8 + c0]       = make_float2(acc[nt][0], acc[nt][1]);
                *(float2*)&gbk[(rowA + 8) * 18 + nt * 8 + c0] = make_float2(acc[nt][2], acc[nt][3]);
            }
        }

        // ---- L1 mma (s >= 1): gates1 partial = Wih1.h0 + Whh1.h1, K-half ----
        if (s >= 1) {
            float acc[2][4];
#pragma unroll
            for (int nt = 0; nt < 2; ++nt)
#pragma unroll
                for (int e = 0; e < 4; ++e) acc[nt][e] = 0.f;
#pragma unroll
            for (int ii = 0; ii < 8; ++ii) {       // Wih1 . h0 (single)
                int kk = ii * 16 + klo;
                unsigned bh[4], ai[4];
                ldsm4(bh, sb + MO_BH0 + bw_off(brow, kk));
                ldsm4(ai, sb + MO_W1I + aw_off(arow, kk));
                mma16816h(acc[0], ai, bh[0], bh[2]);
                mma16816h(acc[1], ai, bh[1], bh[3]);
            }
#pragma unroll
            for (int ii = 0; ii < 8; ++ii) {       // Whh1 . h1 (hi/lo)
                int kk = ii * 16 + klo;
                unsigned bh[4], ah[4], al[4];
                ldsm4(bh, sb + MO_BH1 + bw_off(brow, kk));
                unsigned ka = aw_off(arow, kk);
                ldsm4(ah, sb + MO_W1H + ka);
                ldsm4(al, sb + MO_W1L + ka);
                mma16816h(acc[0], ah, bh[0], bh[2]);
                mma16816h(acc[0], al, bh[0], bh[2]);
                mma16816h(acc[1], ah, bh[1], bh[3]);
                mma16816h(acc[1], al, bh[1], bh[3]);
            }
            float* gbk = kh ? gb3 : gb2;
            int rowA = ws * 16 + (lane >> 2);
            int c0   = 2 * (lane & 3);
#pragma unroll
            for (int nt = 0; nt < 2; ++nt) {
                *(float2*)&gbk[rowA * 18 + nt * 8 + c0]       = make_float2(acc[nt][0], acc[nt][1]);
                *(float2*)&gbk[(rowA + 8) * 18 + nt * 8 + c0] = make_float2(acc[nt][2], acc[nt][3]);
            }
        }

        // prefetch xg for s+1
        float xvn[4] = {0.f, 0.f, 0.f, 0.f};
        if (s + 1 < TQ) {
            const __half* pn2 = xbase + (size_t)(s + 1) * GQ;
#pragma unroll
            for (int g = 0; g < 4; ++g)
                xvn[g] = __half2float(__ldcg(pn2 + (g << 8)));
        }
        __syncthreads();

        // ---- activations + publish ----
        char* baseh = &g_htile[wbuf][bg][0];
        float hn0 = 0.f, cn0 = 0.f, hn1 = 0.f, cn1 = 0.f;
        unsigned hiw1 = 0;

        if (s < TQ) {   // layer 0 produces h0[s]
            float pi = gb0[(jl     ) * 18 + bA] + gb1[(jl     ) * 18 + bA] + xv[0];
            float pf = gb0[(16 + jl) * 18 + bA] + gb1[(16 + jl) * 18 + bA] + xv[1];
            float pg = gb0[(32 + jl) * 18 + bA] + gb1[(32 + jl) * 18 + bA] + xv[2];
            float po = gb0[(48 + jl) * 18 + bA] + gb1[(48 + jl) * 18 + bA] + xv[3];
            float gi = sigf(pi), gf = sigf(pf), gg = tanhf_(pg), go = sigf(po);
            cn0 = gf * cst0 + gi * gg;
            cst0 = cn0;
            hn0 = go * tanhf_(cn0);

            __half hh = __float2half_rn(hn0);
            unsigned pck = (unsigned)*(unsigned short*)&hh;
            unsigned pn  = __shfl_down_sync(0xFFFFFFFFu, pck, 1);
            if ((jl & 1) == 0)
                *(unsigned*)(baseh + bw_off(bA, jg)) = pck | (pn << 16);
        }

        if (s >= 1) {   // layer 1 produces h1[s-1]
            float pi = gb2[(jl     ) * 18 + bA] + gb3[(jl     ) * 18 + bA] + bias1[0];
            float pf = gb2[(16 + jl) * 18 + bA] + gb3[(16 + jl) * 18 + bA] + bias1[1];
            float pg = gb2[(32 + jl) * 18 + bA] + gb3[(32 + jl) * 18 + bA] + bias1[2];
            float po = gb2[(48 + jl) * 18 + bA] + gb3[(48 + jl) * 18 + bA] + bias1[3];
            float gi = sigf(pi), gf = sigf(pf), gg = tanhf_(pg), go = sigf(po);
            cn1 = gf * cst1 + gi * gg;
            cst1 = cn1;
            hn1 = go * tanhf_(cn1);

            __half hh = __float2half_rn(hn1);
            unsigned pck = (unsigned)*(unsigned short*)&hh;
            unsigned pn  = __shfl_down_sync(0xFFFFFFFFu, pck, 1);
            if ((jl & 1) == 0) {
                hiw1 = pck | (pn << 16);
                *(unsigned*)(baseh + 8192 + bw_off(bA, jg)) = hiw1;
            }
        } else {        // s == 0: seed h1[-1] = 0 in wbuf
            if ((jl & 1) == 0)
                *(unsigned*)(baseh + 8192 + bw_off(bA, jg)) = 0u;
        }

        // ---- barrier release ----
        __syncthreads();
        if (tid == 0)
            asm volatile("st.release.gpu.global.u32 [%0], %1;"
                         :: "l"(myflag), "r"((unsigned)(s + 1)) : "memory");

        // deferred bookkeeping (overlaps peer polling)
        if (s >= 1 && (jl & 1) == 0) {
            size_t hoff = ((size_t)(b0 + bA) * TQ + (s - 1)) * HQ + jg;
            *(unsigned*)&g_a16[hoff] = hiw1;
        }
        if (s == TQ - 1) {
            int bgl = b0 + bA;
            outh[bgl * HQ + jg] = hn0;
            outc[bgl * HQ + jg] = cn0;
        }
        if (s == TQ) {
            int bgl = b0 + bA;
            outh[BQ * HQ + bgl * HQ + jg] = hn1;
            outc[BQ * HQ + bgl * HQ + jg] = cn1;
        }

        if (wid == 0 && lane < 16) {
            unsigned v;
            do {
                asm volatile("ld.acquire.gpu.global.u32 %0, [%1];"
                             : "=r"(v) : "l"(pollp) : "memory");
            } while (v < (unsigned)(s + 1));
        }
        __syncthreads();

        xv[0] = xvn[0]; xv[1] = xvn[1]; xv[2] = xvn[2]; xv[3] = xvn[3];
    }
}

// ---------------- launch -----------------------------------------------------
extern "C" void kernel_launch(void* const* d_in, const int* in_sizes, int n_in,
                              void* d_out, int out_size)
{
    const float* x    = (const float*)d_in[0];
    const float* wih0 = (const float*)d_in[1];
    const float* whh0 = (const float*)d_in[2];
    const float* bih0 = (const float*)d_in[3];
    const float* bhh0 = (const float*)d_in[4];
    const float* wih1 = (const float*)d_in[5];
    const float* whh1 = (const float*)d_in[6];
    const float* bih1 = (const float*)d_in[7];
    const float* bhh1 = (const float*)d_in[8];
    const float* wlin = (const float*)d_in[9];
    const float* blin = (const float*)d_in[10];

    float* out  = (float*)d_out;                    // [B,T,In]
    float* outh = out + (size_t)BQ * TQ * INQ;      // [2,B,H]
    float* outc = outh + 2 * BQ * HQ;               // [2,B,H]

    __half *p_xg, *p_a16, *p_whi, *p_wlo;
    cudaGetSymbolAddress((void**)&p_xg,  g_xg16);
    cudaGetSymbolAddress((void**)&p_a16, g_a16);
    cudaGetSymbolAddress((void**)&p_whi, g_whi);
    cudaGetSymbolAddress((void**)&p_wlo, g_wlo);
    cudaFuncSetAttribute(gemm_pp,    cudaFuncAttributeMaxDynamicSharedMemorySize, GEMM_SMEM);
    cudaFuncSetAttribute(lstm_fused, cudaFuncAttributeMaxDynamicSharedMemorySize, LSTM_SMEM_F);

    dim3 gg(GQ / 256, MROWS / 128);    // (4, 1024)
    dim3 gf(1, MROWS / 128);           // N=128 -> nsub=1

    const int CB = 256;
    int n4x = MROWS * INQ / 4;

    // layer-0 input GEMM
    cvt_a<<<(n4x + CB - 1) / CB, CB>>>((const float4*)x, (uint2*)p_a16, n4x);
    cvt_w<<<(GQ * INQ / 4 + CB - 1) / CB, CB>>>((const float4*)wih0, (uint2*)p_whi, (uint2*)p_wlo, GQ * INQ / 4);
    init_kernel<<<64, 256>>>();
    gemm_pp<<<gg, 256, GEMM_SMEM>>>(p_a16, p_whi, p_wlo, bih0, bhh0, (float*)p_xg, MROWS, GQ, INQ, 1);

    // fused 2-layer recurrence (writes h1seq as fp16 into g_a16)
    lstm_fused<<<LGRID, 256, LSTM_SMEM_F>>>(p_xg, whh0, wih1, whh1, bih1, bhh1, outh, outc);

    // final projection (fp32 out)
    cvt_w<<<(INQ * HQ / 4 + CB - 1) / CB, CB>>>((const float4*)wlin, (uint2*)p_whi, (uint2*)p_wlo, INQ * HQ / 4);
    gemm_pp<<<gf, 256, GEMM_SMEM>>>(p_a16, p_whi, p_wlo, blin, nullptr, out, MROWS, INQ, HQ, 0);
}